// round 1
// baseline (speedup 1.0000x reference)
#include <cuda_runtime.h>

#define HH 256
#define WW 256
#define HWP 65536
#define CC 64
#define BB 4

// Scratch (allocation-free: __device__ globals)
__device__ float g_qkv[(size_t)BB * 192 * HWP];   // [b][o][h*W+w], o: q=0..63,k=64..127,v=128..191
__device__ float g_t[(size_t)BB * CC * HWP];      // attention output + residual

// ---------------------------------------------------------------------------
// Kernel 1: qkv[b,o,p] = sum_c w_qkv[o,c] * x[b,c,p] + b_qkv[o]
// Block: 64 outputs x 64 pixels, 256 threads, 4x4 register tile per thread.
// ---------------------------------------------------------------------------
__global__ __launch_bounds__(256) void qkv_kernel(const float* __restrict__ x,
                                                  const float* __restrict__ wq,
                                                  const float* __restrict__ bq) {
    __shared__ float ws[64 * 64];   // straight copy of w_qkv slice: [o][c]
    __shared__ float xs[64 * 64];   // [c][p]

    const int p0  = blockIdx.x * 64;
    const int oc0 = blockIdx.y * 64;
    const int b   = blockIdx.z;
    const int tid = threadIdx.x;

    // Stage weights (coalesced straight copy) and x tile
    #pragma unroll
    for (int i = 0; i < 16; i++)
        ws[tid + i * 256] = wq[oc0 * 64 + tid + i * 256];

    const float* xb = x + (size_t)b * CC * HWP + p0;
    #pragma unroll
    for (int i = 0; i < 16; i++) {
        int e = tid + i * 256;
        int c = e >> 6, p = e & 63;
        xs[e] = xb[(size_t)c * HWP + p];
    }
    __syncthreads();

    const int og = tid >> 4;     // 16 groups of 4 output channels
    const int pg = tid & 15;     // 16 groups of 4 pixels

    float acc[4][4];
    #pragma unroll
    for (int i = 0; i < 4; i++) {
        float bv = bq[oc0 + og * 4 + i];
        #pragma unroll
        for (int j = 0; j < 4; j++) acc[i][j] = bv;
    }

    #pragma unroll 8
    for (int c = 0; c < 64; c++) {
        float4 xv = *(const float4*)&xs[c * 64 + pg * 4];
        float w0 = ws[(og * 4 + 0) * 64 + c];
        float w1 = ws[(og * 4 + 1) * 64 + c];
        float w2 = ws[(og * 4 + 2) * 64 + c];
        float w3 = ws[(og * 4 + 3) * 64 + c];
        acc[0][0] += w0 * xv.x; acc[0][1] += w0 * xv.y; acc[0][2] += w0 * xv.z; acc[0][3] += w0 * xv.w;
        acc[1][0] += w1 * xv.x; acc[1][1] += w1 * xv.y; acc[1][2] += w1 * xv.z; acc[1][3] += w1 * xv.w;
        acc[2][0] += w2 * xv.x; acc[2][1] += w2 * xv.y; acc[2][2] += w2 * xv.z; acc[2][3] += w2 * xv.w;
        acc[3][0] += w3 * xv.x; acc[3][1] += w3 * xv.y; acc[3][2] += w3 * xv.z; acc[3][3] += w3 * xv.w;
    }

    float* ob = g_qkv + ((size_t)b * 192 + oc0) * HWP + p0;
    #pragma unroll
    for (int i = 0; i < 4; i++) {
        float4 v = make_float4(acc[i][0], acc[i][1], acc[i][2], acc[i][3]);
        *(float4*)&ob[(size_t)(og * 4 + i) * HWP + pg * 4] = v;
    }
}

// ---------------------------------------------------------------------------
// Kernel 2: window attention (K=3, zero-padded patches) + residual.
// 16x16 pixel tile per block, 1 thread per pixel. One 64x18x18 halo buffer
// in dynamic smem, used first for k (dots), then reloaded with v (aggregate).
// ---------------------------------------------------------------------------
__global__ __launch_bounds__(256) void attn_kernel(const float* __restrict__ x) {
    extern __shared__ float sb[];   // 64 * 324 floats

    const int tid = threadIdx.x;
    const int lx = tid & 15, ly = tid >> 4;
    const int w0 = blockIdx.x * 16, h0 = blockIdx.y * 16;
    const int b = blockIdx.z;
    const int hh = h0 + ly, ww = w0 + lx;
    const int p = hh * WW + ww;

    // --- load k halo (zero padded) ---
    const float* kb = g_qkv + ((size_t)b * 192 + 64) * HWP;
    for (int e = tid; e < 64 * 324; e += 256) {
        int c = e / 324; int r = e - c * 324;
        int yy = r / 18;  int xx = r - yy * 18;
        int gy = h0 - 1 + yy, gx = w0 - 1 + xx;
        sb[e] = (gy >= 0 && gy < HH && gx >= 0 && gx < WW)
                    ? kb[(size_t)c * HWP + gy * WW + gx] : 0.0f;
    }
    __syncthreads();

    float d[9];
    #pragma unroll
    for (int n = 0; n < 9; n++) d[n] = 0.0f;

    const float* qb = g_qkv + (size_t)b * 192 * HWP + p;
    #pragma unroll 4
    for (int c = 0; c < 64; c++) {
        float qc = qb[(size_t)c * HWP];
        const float* kr = &sb[c * 324 + ly * 18 + lx];
        d[0] += qc * kr[0];  d[1] += qc * kr[1];  d[2] += qc * kr[2];
        d[3] += qc * kr[18]; d[4] += qc * kr[19]; d[5] += qc * kr[20];
        d[6] += qc * kr[36]; d[7] += qc * kr[37]; d[8] += qc * kr[38];
    }

    // softmax over 9 taps (scale = C^-0.5 = 0.125); OOB taps contribute dot=0
    float m = -1e30f;
    #pragma unroll
    for (int n = 0; n < 9; n++) { d[n] *= 0.125f; m = fmaxf(m, d[n]); }
    float s = 0.0f;
    #pragma unroll
    for (int n = 0; n < 9; n++) { d[n] = expf(d[n] - m); s += d[n]; }
    float inv = 1.0f / s;
    #pragma unroll
    for (int n = 0; n < 9; n++) d[n] *= inv;

    __syncthreads();   // done reading k

    // --- reload halo with v ---
    const float* vb = g_qkv + ((size_t)b * 192 + 128) * HWP;
    for (int e = tid; e < 64 * 324; e += 256) {
        int c = e / 324; int r = e - c * 324;
        int yy = r / 18;  int xx = r - yy * 18;
        int gy = h0 - 1 + yy, gx = w0 - 1 + xx;
        sb[e] = (gy >= 0 && gy < HH && gx >= 0 && gx < WW)
                    ? vb[(size_t)c * HWP + gy * WW + gx] : 0.0f;
    }
    __syncthreads();

    const float* xb = x + (size_t)b * CC * HWP + p;
    float* tb = g_t + (size_t)b * CC * HWP + p;
    #pragma unroll 2
    for (int c = 0; c < 64; c++) {
        const float* vr = &sb[c * 324 + ly * 18 + lx];
        float a = d[0] * vr[0]  + d[1] * vr[1]  + d[2] * vr[2]
                + d[3] * vr[18] + d[4] * vr[19] + d[5] * vr[20]
                + d[6] * vr[36] + d[7] * vr[37] + d[8] * vr[38];
        tb[(size_t)c * HWP] = a + xb[(size_t)c * HWP];
    }
}

// ---------------------------------------------------------------------------
// Kernel 3: 3x3 conv (64->64, pad 1, no bias) + ReLU.
// Full weight tensor (147 KB) resident in smem; per-channel 6x34 input halo
// tile double-buffered. 256 threads: 8 warps x (8 oc each), 32x4 pixel tile,
// 8oc x 4px register tile -> 288 FFMA vs ~90 LDS per channel (FFMA-bound).
// ---------------------------------------------------------------------------
__global__ __launch_bounds__(256) void conv_kernel(const float* __restrict__ wm,
                                                   float* __restrict__ out) {
    extern __shared__ float smem[];
    float* sw  = smem;              // 36864 floats, straight copy of w_mlp [o][c][tap]
    float* ib0 = smem + 36864;      // 204 floats (padded 208)
    float* ib1 = ib0 + 208;

    const int tid = threadIdx.x;
    const int wt0 = blockIdx.x * 32, ht0 = blockIdx.y * 4;
    const int b = blockIdx.z;

    for (int g = tid; g < 36864; g += 256) sw[g] = wm[g];

    const float* tb = g_t + (size_t)b * CC * HWP;

    // staging-thread geometry (6 rows x 34 cols halo tile)
    const bool ok = tid < 204;
    const int yy = tid / 34, xx = tid - yy * 34;
    const int gy = ht0 - 1 + yy, gx = wt0 - 1 + xx;
    const bool inb = ok && gy >= 0 && gy < HH && gx >= 0 && gx < WW;
    const int gofs = gy * WW + gx;

    // stage c = 0
    float pre = inb ? tb[gofs] : 0.0f;
    if (ok) ib0[tid] = pre;
    __syncthreads();

    const int og = tid >> 5;              // warp id -> oc base og*8 (warp-uniform)
    const int pg = tid & 31;
    const int prow = pg >> 3;             // pixel row 0..3
    const int pc4 = (pg & 7) << 2;        // pixel col base (x4)

    float acc[8][4];
    #pragma unroll
    for (int i = 0; i < 8; i++)
        #pragma unroll
        for (int j = 0; j < 4; j++) acc[i][j] = 0.0f;

    const int wbase = og * 8 * 576;

    for (int c = 0; c < 64; c++) {
        const float* ib = (c & 1) ? ib1 : ib0;

        // prefetch next channel's halo tile (latency hidden by compute)
        if (c < 63) pre = inb ? tb[(size_t)(c + 1) * HWP + gofs] : 0.0f;

        // input registers: 3 tap-rows x 6 cols
        float iv[3][6];
        #pragma unroll
        for (int dy = 0; dy < 3; dy++)
            #pragma unroll
            for (int j = 0; j < 6; j++)
                iv[dy][j] = ib[(prow + dy) * 34 + pc4 + j];

        #pragma unroll
        for (int ky = 0; ky < 3; ky++)
            #pragma unroll
            for (int kx = 0; kx < 3; kx++) {
                const int tap = ky * 3 + kx;
                #pragma unroll
                for (int i = 0; i < 8; i++) {
                    float wv = sw[wbase + i * 576 + c * 9 + tap];   // warp-uniform broadcast
                    #pragma unroll
                    for (int j = 0; j < 4; j++)
                        acc[i][j] += wv * iv[ky][kx + j];
                }
            }

        if (c < 63) {
            float* nib = (c & 1) ? ib0 : ib1;   // write the OTHER buffer
            if (ok) nib[tid] = pre;
        }
        __syncthreads();
    }

    float* ob = out + (size_t)b * CC * HWP + (ht0 + prow) * WW + wt0 + pc4;
    #pragma unroll
    for (int i = 0; i < 8; i++) {
        float4 v = make_float4(fmaxf(acc[i][0], 0.0f), fmaxf(acc[i][1], 0.0f),
                               fmaxf(acc[i][2], 0.0f), fmaxf(acc[i][3], 0.0f));
        *(float4*)&ob[(size_t)(og * 8 + i) * HWP] = v;
    }
}

// ---------------------------------------------------------------------------
extern "C" void kernel_launch(void* const* d_in, const int* in_sizes, int n_in,
                              void* d_out, int out_size) {
    const float* x     = (const float*)d_in[0];   // [4,64,256,256]
    const float* w_qkv = (const float*)d_in[1];   // [192,64]
    const float* b_qkv = (const float*)d_in[2];   // [192]
    const float* w_mlp = (const float*)d_in[3];   // [64,64,3,3]
    float* out = (float*)d_out;

    const int SMEM2 = 64 * 324 * 4;                    // 82944 B
    const int SMEM3 = (36864 + 2 * 208) * 4;           // 149120 B
    cudaFuncSetAttribute(attn_kernel, cudaFuncAttributeMaxDynamicSharedMemorySize, SMEM2);
    cudaFuncSetAttribute(conv_kernel, cudaFuncAttributeMaxDynamicSharedMemorySize, SMEM3);

    qkv_kernel<<<dim3(HWP / 64, 3, BB), 256>>>(x, w_qkv, b_qkv);
    attn_kernel<<<dim3(WW / 16, HH / 16, BB), 256, SMEM2>>>(x);
    conv_kernel<<<dim3(WW / 32, HH / 4, BB), 256, SMEM3>>>(w_mlp, out);
}

// round 2
// speedup vs baseline: 1.0158x; 1.0158x over previous
#include <cuda_runtime.h>

#define HH 256
#define WW 256
#define HWP 65536
#define CC 64
#define BB 4

typedef unsigned long long u64;

#define PACK2(out, lo, hi) \
    asm("mov.b64 %0, {%1, %2};" : "=l"(out) : "f"(lo), "f"(hi))
#define UNPACK2(lo, hi, in) \
    asm("mov.b64 {%0, %1}, %2;" : "=f"(lo), "=f"(hi) : "l"(in))
#define FMA2(d, a, b, c) \
    asm("fma.rn.f32x2 %0, %1, %2, %3;" : "=l"(d) : "l"(a), "l"(b), "l"(c))

// Scratch (allocation-free: __device__ globals)
__device__ float g_qkv[(size_t)BB * 192 * HWP];   // [b][o][p]  q:0-63 k:64-127 v:128-191
__device__ float g_t[(size_t)BB * CC * HWP];      // attention output + residual

// ---------------------------------------------------------------------------
// Kernel 1: qkv = w_qkv @ x + b  (packed f32x2: oc-pair accumulators)
// ---------------------------------------------------------------------------
__global__ __launch_bounds__(256) void qkv_kernel(const float* __restrict__ x,
                                                  const float* __restrict__ wq,
                                                  const float* __restrict__ bq) {
    __shared__ float ws[64 * 66];   // transposed [c][o], pad 66 (8B-aligned rows)
    __shared__ float xs[64 * 64];   // [c][p]

    const int p0  = blockIdx.x * 64;
    const int oc0 = blockIdx.y * 64;
    const int b   = blockIdx.z;
    const int tid = threadIdx.x;

    #pragma unroll
    for (int i = 0; i < 16; i++) {
        int e = tid + i * 256;
        int o = e >> 6, c = e & 63;
        ws[c * 66 + o] = wq[oc0 * 64 + e];     // read coalesced, transpose on store
    }
    const float* xb = x + (size_t)b * CC * HWP + p0;
    #pragma unroll
    for (int i = 0; i < 16; i++) {
        int e = tid + i * 256;
        int c = e >> 6, p = e & 63;
        xs[e] = xb[(size_t)c * HWP + p];
    }
    __syncthreads();

    const int og = tid >> 4;     // 16 groups of 4 output channels (2 oc-pairs)
    const int pg = tid & 15;     // 16 groups of 4 pixels

    u64 acc[2][4];
    {
        float b0 = bq[oc0 + og * 4 + 0], b1 = bq[oc0 + og * 4 + 1];
        float b2 = bq[oc0 + og * 4 + 2], b3 = bq[oc0 + og * 4 + 3];
        u64 p01, p23;
        PACK2(p01, b0, b1); PACK2(p23, b2, b3);
        #pragma unroll
        for (int j = 0; j < 4; j++) { acc[0][j] = p01; acc[1][j] = p23; }
    }

    #pragma unroll 4
    for (int c = 0; c < 64; c++) {
        float4 xv = *(const float4*)&xs[c * 64 + pg * 4];
        u64 sx0, sx1, sx2, sx3;
        PACK2(sx0, xv.x, xv.x); PACK2(sx1, xv.y, xv.y);
        PACK2(sx2, xv.z, xv.z); PACK2(sx3, xv.w, xv.w);
        const u64* wp = (const u64*)&ws[c * 66 + og * 4];
        u64 w0 = wp[0], w1 = wp[1];
        FMA2(acc[0][0], w0, sx0, acc[0][0]);
        FMA2(acc[0][1], w0, sx1, acc[0][1]);
        FMA2(acc[0][2], w0, sx2, acc[0][2]);
        FMA2(acc[0][3], w0, sx3, acc[0][3]);
        FMA2(acc[1][0], w1, sx0, acc[1][0]);
        FMA2(acc[1][1], w1, sx1, acc[1][1]);
        FMA2(acc[1][2], w1, sx2, acc[1][2]);
        FMA2(acc[1][3], w1, sx3, acc[1][3]);
    }

    float* ob = g_qkv + ((size_t)b * 192 + oc0) * HWP + p0;
    #pragma unroll
    for (int i = 0; i < 2; i++) {
        float lo0, hi0, lo1, hi1, lo2, hi2, lo3, hi3;
        UNPACK2(lo0, hi0, acc[i][0]); UNPACK2(lo1, hi1, acc[i][1]);
        UNPACK2(lo2, hi2, acc[i][2]); UNPACK2(lo3, hi3, acc[i][3]);
        float4 vlo = make_float4(lo0, lo1, lo2, lo3);
        float4 vhi = make_float4(hi0, hi1, hi2, hi3);
        *(float4*)&ob[(size_t)(og * 4 + i * 2 + 0) * HWP + pg * 4] = vlo;
        *(float4*)&ob[(size_t)(og * 4 + i * 2 + 1) * HWP + pg * 4] = vhi;
    }
}

// ---------------------------------------------------------------------------
// Kernel 2: window attention (K=3, zero-padded) + residual. (unchanged)
// ---------------------------------------------------------------------------
__global__ __launch_bounds__(256) void attn_kernel(const float* __restrict__ x) {
    extern __shared__ float sb[];   // 64 * 324 floats

    const int tid = threadIdx.x;
    const int lx = tid & 15, ly = tid >> 4;
    const int w0 = blockIdx.x * 16, h0 = blockIdx.y * 16;
    const int b = blockIdx.z;
    const int hh = h0 + ly, ww = w0 + lx;
    const int p = hh * WW + ww;

    const float* kb = g_qkv + ((size_t)b * 192 + 64) * HWP;
    for (int e = tid; e < 64 * 324; e += 256) {
        int c = e / 324; int r = e - c * 324;
        int yy = r / 18;  int xx = r - yy * 18;
        int gy = h0 - 1 + yy, gx = w0 - 1 + xx;
        sb[e] = (gy >= 0 && gy < HH && gx >= 0 && gx < WW)
                    ? kb[(size_t)c * HWP + gy * WW + gx] : 0.0f;
    }
    __syncthreads();

    float d[9];
    #pragma unroll
    for (int n = 0; n < 9; n++) d[n] = 0.0f;

    const float* qb = g_qkv + (size_t)b * 192 * HWP + p;
    #pragma unroll 4
    for (int c = 0; c < 64; c++) {
        float qc = qb[(size_t)c * HWP];
        const float* kr = &sb[c * 324 + ly * 18 + lx];
        d[0] += qc * kr[0];  d[1] += qc * kr[1];  d[2] += qc * kr[2];
        d[3] += qc * kr[18]; d[4] += qc * kr[19]; d[5] += qc * kr[20];
        d[6] += qc * kr[36]; d[7] += qc * kr[37]; d[8] += qc * kr[38];
    }

    float m = -1e30f;
    #pragma unroll
    for (int n = 0; n < 9; n++) { d[n] *= 0.125f; m = fmaxf(m, d[n]); }
    float s = 0.0f;
    #pragma unroll
    for (int n = 0; n < 9; n++) { d[n] = expf(d[n] - m); s += d[n]; }
    float inv = 1.0f / s;
    #pragma unroll
    for (int n = 0; n < 9; n++) d[n] *= inv;

    __syncthreads();

    const float* vb = g_qkv + ((size_t)b * 192 + 128) * HWP;
    for (int e = tid; e < 64 * 324; e += 256) {
        int c = e / 324; int r = e - c * 324;
        int yy = r / 18;  int xx = r - yy * 18;
        int gy = h0 - 1 + yy, gx = w0 - 1 + xx;
        sb[e] = (gy >= 0 && gy < HH && gx >= 0 && gx < WW)
                    ? vb[(size_t)c * HWP + gy * WW + gx] : 0.0f;
    }
    __syncthreads();

    const float* xb = x + (size_t)b * CC * HWP + p;
    float* tb = g_t + (size_t)b * CC * HWP + p;
    #pragma unroll 2
    for (int c = 0; c < 64; c++) {
        const float* vr = &sb[c * 324 + ly * 18 + lx];
        float a = d[0] * vr[0]  + d[1] * vr[1]  + d[2] * vr[2]
                + d[3] * vr[18] + d[4] * vr[19] + d[5] * vr[20]
                + d[6] * vr[36] + d[7] * vr[37] + d[8] * vr[38];
        tb[(size_t)c * HWP] = a + xb[(size_t)c * HWP];
    }
}

// ---------------------------------------------------------------------------
// Kernel 3: 3x3 conv (64->64, pad 1) + ReLU, packed f32x2.
// All 64 channel halos (6x35, conflict-free stride) + full transposed weight
// tensor resident in smem. No syncthreads in the main loop.
// 256 thr: 8 warps x 8 oc (4 oc-pairs), 32x4 px tile, 4px per thread.
// Per channel/thread: 144 FMA2 + 18 splat(ALU) + 36 LDS64(bcast) + 18 LDS32.
// ---------------------------------------------------------------------------
#define WSTR 66                    // padded oc-row stride for weights
#define HSTR 35                    // padded halo row stride (conflict-free)
#define CHHALO (6 * HSTR)          // 210 floats per channel
#define SW_FLOATS (64 * 9 * WSTR)  // 38016
#define HB_FLOATS (64 * CHHALO)    // 13440

__global__ __launch_bounds__(256) void conv_kernel(const float* __restrict__ wm,
                                                   float* __restrict__ out) {
    extern __shared__ float smem[];
    float* sw = smem;               // [(c*9+tap)*66 + o]
    float* hb = smem + SW_FLOATS;   // [c*210 + row*35 + col]

    const int tid = threadIdx.x;
    const int wt0 = blockIdx.x * 32, ht0 = blockIdx.y * 4;
    const int b = blockIdx.z;

    // stage weights, transposed to [c][tap][o] (reads coalesced)
    for (int e = tid; e < 36864; e += 256) {
        int o = e / 576; int rem = e - o * 576;   // rem = c*9+tap
        sw[rem * WSTR + o] = wm[e];
    }
    // stage all 64 channel halos (zero padded)
    const float* tb = g_t + (size_t)b * CC * HWP;
    for (int e = tid; e < HB_FLOATS; e += 256) {
        int c = e / CHHALO; int r = e - c * CHHALO;
        int yy = r / HSTR;  int xx = r - yy * HSTR;
        float v = 0.0f;
        if (xx < 34) {
            int gy = ht0 - 1 + yy, gx = wt0 - 1 + xx;
            if (gy >= 0 && gy < HH && gx >= 0 && gx < WW)
                v = tb[(size_t)c * HWP + gy * WW + gx];
        }
        hb[e] = v;
    }
    __syncthreads();

    const int og = tid >> 5;              // warp id (warp-uniform oc base og*8)
    const int pg = tid & 31;
    const int prow = pg >> 3;             // pixel row 0..3
    const int pc4 = (pg & 7) << 2;        // pixel col base

    u64 acc[4][4];                        // [oc-pair][px] — packed (oc, oc+1)
    #pragma unroll
    for (int i = 0; i < 4; i++)
        #pragma unroll
        for (int j = 0; j < 4; j++) acc[i][j] = 0ULL;

    #pragma unroll 1
    for (int c = 0; c < 64; c++) {
        // splat-packed input window (3 tap-rows x 6 cols)
        u64 sv[3][6];
        const float* hc = &hb[c * CHHALO + prow * HSTR + pc4];
        #pragma unroll
        for (int dy = 0; dy < 3; dy++)
            #pragma unroll
            for (int j = 0; j < 6; j++) {
                float t = hc[dy * HSTR + j];
                PACK2(sv[dy][j], t, t);
            }

        const float* wc = &sw[c * 9 * WSTR + og * 8];
        #pragma unroll
        for (int ky = 0; ky < 3; ky++)
            #pragma unroll
            for (int kx = 0; kx < 3; kx++) {
                const u64* wp = (const u64*)&wc[(ky * 3 + kx) * WSTR];
                #pragma unroll
                for (int i = 0; i < 4; i++) {
                    u64 w2 = wp[i];       // (w[oc], w[oc+1]) — warp-uniform bcast
                    FMA2(acc[i][0], w2, sv[ky][kx + 0], acc[i][0]);
                    FMA2(acc[i][1], w2, sv[ky][kx + 1], acc[i][1]);
                    FMA2(acc[i][2], w2, sv[ky][kx + 2], acc[i][2]);
                    FMA2(acc[i][3], w2, sv[ky][kx + 3], acc[i][3]);
                }
            }
    }

    float* ob = out + (size_t)b * CC * HWP + (ht0 + prow) * WW + wt0 + pc4;
    #pragma unroll
    for (int i = 0; i < 4; i++) {
        float lo0, hi0, lo1, hi1, lo2, hi2, lo3, hi3;
        UNPACK2(lo0, hi0, acc[i][0]); UNPACK2(lo1, hi1, acc[i][1]);
        UNPACK2(lo2, hi2, acc[i][2]); UNPACK2(lo3, hi3, acc[i][3]);
        float4 vlo = make_float4(fmaxf(lo0, 0.f), fmaxf(lo1, 0.f),
                                 fmaxf(lo2, 0.f), fmaxf(lo3, 0.f));
        float4 vhi = make_float4(fmaxf(hi0, 0.f), fmaxf(hi1, 0.f),
                                 fmaxf(hi2, 0.f), fmaxf(hi3, 0.f));
        *(float4*)&ob[(size_t)(og * 8 + i * 2 + 0) * HWP] = vlo;
        *(float4*)&ob[(size_t)(og * 8 + i * 2 + 1) * HWP] = vhi;
    }
}

// ---------------------------------------------------------------------------
extern "C" void kernel_launch(void* const* d_in, const int* in_sizes, int n_in,
                              void* d_out, int out_size) {
    const float* x     = (const float*)d_in[0];   // [4,64,256,256]
    const float* w_qkv = (const float*)d_in[1];   // [192,64]
    const float* b_qkv = (const float*)d_in[2];   // [192]
    const float* w_mlp = (const float*)d_in[3];   // [64,64,3,3]
    float* out = (float*)d_out;

    const int SMEM2 = 64 * 324 * 4;                         // 82944 B
    const int SMEM3 = (SW_FLOATS + HB_FLOATS) * 4;          // 205824 B
    cudaFuncSetAttribute(attn_kernel, cudaFuncAttributeMaxDynamicSharedMemorySize, SMEM2);
    cudaFuncSetAttribute(conv_kernel, cudaFuncAttributeMaxDynamicSharedMemorySize, SMEM3);

    qkv_kernel<<<dim3(HWP / 64, 3, BB), 256>>>(x, w_qkv, b_qkv);
    attn_kernel<<<dim3(WW / 16, HH / 16, BB), 256, SMEM2>>>(x);
    conv_kernel<<<dim3(WW / 32, HH / 4, BB), 256, SMEM3>>>(w_mlp, out);
}

// round 4
// speedup vs baseline: 1.3535x; 1.3324x over previous
#include <cuda_runtime.h>
#include <cuda_bf16.h>
#include <cstdint>

#define HH 256
#define WW 256
#define HWP 65536
#define CC 64
#define BB 4

// ---------------------------------------------------------------- scratch
__device__ float g_qkv[(size_t)BB * 192 * HWP];                      // [b][o][p]
__device__ __align__(16) __nv_bfloat16 g_th[(size_t)BB * HWP * CC];  // [b][p][c] hi
__device__ __align__(16) __nv_bfloat16 g_tl[(size_t)BB * HWP * CC];  // [b][p][c] lo
__device__ __align__(16) __nv_bfloat16 g_wh[9 * 4096];               // [tap][oc][c] hi
__device__ __align__(16) __nv_bfloat16 g_wl[9 * 4096];               // [tap][oc][c] lo

// ---------------------------------------------------------------------------
// mma.sync m16n8k16 bf16 (baseline PTX, sm_80+)
// ---------------------------------------------------------------------------
__device__ __forceinline__ void mma16816(float& d0, float& d1, float& d2, float& d3,
                                         uint32_t a0, uint32_t a1, uint32_t a2, uint32_t a3,
                                         uint32_t b0, uint32_t b1) {
    asm volatile(
        "mma.sync.aligned.m16n8k16.row.col.f32.bf16.bf16.f32 "
        "{%0,%1,%2,%3}, {%4,%5,%6,%7}, {%8,%9}, {%0,%1,%2,%3};"
        : "+f"(d0), "+f"(d1), "+f"(d2), "+f"(d3)
        : "r"(a0), "r"(a1), "r"(a2), "r"(a3), "r"(b0), "r"(b1));
}

// ---------------------------------------------------------------------------
// Kernel 0: weight prep -> bf16 hi/lo, layout [tap][oc][c]
// ---------------------------------------------------------------------------
__global__ void wprep_kernel(const float* __restrict__ wm) {
    int e = blockIdx.x * 256 + threadIdx.x;
    if (e >= 9 * 4096) return;
    int tap = e >> 12, rem = e & 4095;
    int oc = rem >> 6, c = rem & 63;
    float w = wm[oc * 576 + c * 9 + tap];
    __nv_bfloat16 hi = __float2bfloat16_rn(w);
    __nv_bfloat16 lo = __float2bfloat16_rn(w - __bfloat162float(hi));
    g_wh[tap * 4096 + oc * 64 + c] = hi;
    g_wl[tap * 4096 + oc * 64 + c] = lo;
}

// ---------------------------------------------------------------------------
// Kernel 1: qkv = w_qkv @ x + b (scalar fp32)
// ---------------------------------------------------------------------------
__global__ __launch_bounds__(256) void qkv_kernel(const float* __restrict__ x,
                                                  const float* __restrict__ wq,
                                                  const float* __restrict__ bq) {
    __shared__ float ws[64 * 64];
    __shared__ float xs[64 * 64];
    const int p0 = blockIdx.x * 64, oc0 = blockIdx.y * 64, b = blockIdx.z;
    const int tid = threadIdx.x;

    #pragma unroll
    for (int i = 0; i < 16; i++) ws[tid + i * 256] = wq[oc0 * 64 + tid + i * 256];
    const float* xb = x + (size_t)b * CC * HWP + p0;
    #pragma unroll
    for (int i = 0; i < 16; i++) {
        int e = tid + i * 256; int c = e >> 6, p = e & 63;
        xs[e] = xb[(size_t)c * HWP + p];
    }
    __syncthreads();

    const int og = tid >> 4, pg = tid & 15;
    float acc[4][4];
    #pragma unroll
    for (int i = 0; i < 4; i++) {
        float bv = bq[oc0 + og * 4 + i];
        #pragma unroll
        for (int j = 0; j < 4; j++) acc[i][j] = bv;
    }
    #pragma unroll 8
    for (int c = 0; c < 64; c++) {
        float4 xv = *(const float4*)&xs[c * 64 + pg * 4];
        float w0 = ws[(og * 4 + 0) * 64 + c], w1 = ws[(og * 4 + 1) * 64 + c];
        float w2 = ws[(og * 4 + 2) * 64 + c], w3 = ws[(og * 4 + 3) * 64 + c];
        acc[0][0] += w0 * xv.x; acc[0][1] += w0 * xv.y; acc[0][2] += w0 * xv.z; acc[0][3] += w0 * xv.w;
        acc[1][0] += w1 * xv.x; acc[1][1] += w1 * xv.y; acc[1][2] += w1 * xv.z; acc[1][3] += w1 * xv.w;
        acc[2][0] += w2 * xv.x; acc[2][1] += w2 * xv.y; acc[2][2] += w2 * xv.z; acc[2][3] += w2 * xv.w;
        acc[3][0] += w3 * xv.x; acc[3][1] += w3 * xv.y; acc[3][2] += w3 * xv.z; acc[3][3] += w3 * xv.w;
    }
    float* ob = g_qkv + ((size_t)b * 192 + oc0) * HWP + p0;
    #pragma unroll
    for (int i = 0; i < 4; i++) {
        float4 v = make_float4(acc[i][0], acc[i][1], acc[i][2], acc[i][3]);
        *(float4*)&ob[(size_t)(og * 4 + i) * HWP + pg * 4] = v;
    }
}

// ---------------------------------------------------------------------------
// Kernel 2: window attention + residual; writes bf16 hi/lo channel-last.
// ---------------------------------------------------------------------------
__global__ __launch_bounds__(256) void attn_kernel(const float* __restrict__ x) {
    extern __shared__ float sb[];   // 64 * 324

    const int tid = threadIdx.x;
    const int lx = tid & 15, ly = tid >> 4;
    const int w0 = blockIdx.x * 16, h0 = blockIdx.y * 16;
    const int b = blockIdx.z;
    const int p = (h0 + ly) * WW + (w0 + lx);

    const float* kb = g_qkv + ((size_t)b * 192 + 64) * HWP;
    for (int e = tid; e < 64 * 324; e += 256) {
        int c = e / 324, r = e - c * 324, yy = r / 18, xx = r - yy * 18;
        int gy = h0 - 1 + yy, gx = w0 - 1 + xx;
        sb[e] = (gy >= 0 && gy < HH && gx >= 0 && gx < WW)
                    ? kb[(size_t)c * HWP + gy * WW + gx] : 0.0f;
    }
    __syncthreads();

    float d[9];
    #pragma unroll
    for (int n = 0; n < 9; n++) d[n] = 0.0f;
    const float* qb = g_qkv + (size_t)b * 192 * HWP + p;
    #pragma unroll 4
    for (int c = 0; c < 64; c++) {
        float qc = qb[(size_t)c * HWP];
        const float* kr = &sb[c * 324 + ly * 18 + lx];
        d[0] += qc * kr[0];  d[1] += qc * kr[1];  d[2] += qc * kr[2];
        d[3] += qc * kr[18]; d[4] += qc * kr[19]; d[5] += qc * kr[20];
        d[6] += qc * kr[36]; d[7] += qc * kr[37]; d[8] += qc * kr[38];
    }
    float m = -1e30f;
    #pragma unroll
    for (int n = 0; n < 9; n++) { d[n] *= 0.125f; m = fmaxf(m, d[n]); }
    float s = 0.0f;
    #pragma unroll
    for (int n = 0; n < 9; n++) { d[n] = expf(d[n] - m); s += d[n]; }
    float inv = 1.0f / s;
    #pragma unroll
    for (int n = 0; n < 9; n++) d[n] *= inv;
    __syncthreads();

    const float* vb = g_qkv + ((size_t)b * 192 + 128) * HWP;
    for (int e = tid; e < 64 * 324; e += 256) {
        int c = e / 324, r = e - c * 324, yy = r / 18, xx = r - yy * 18;
        int gy = h0 - 1 + yy, gx = w0 - 1 + xx;
        sb[e] = (gy >= 0 && gy < HH && gx >= 0 && gx < WW)
                    ? vb[(size_t)c * HWP + gy * WW + gx] : 0.0f;
    }
    __syncthreads();

    const float* xb = x + (size_t)b * CC * HWP + p;
    __nv_bfloat16* th = g_th + ((size_t)b * HWP + p) * 64;
    __nv_bfloat16* tl = g_tl + ((size_t)b * HWP + p) * 64;
    #pragma unroll 2
    for (int c = 0; c < 64; c++) {
        const float* vr = &sb[c * 324 + ly * 18 + lx];
        float a = d[0] * vr[0]  + d[1] * vr[1]  + d[2] * vr[2]
                + d[3] * vr[18] + d[4] * vr[19] + d[5] * vr[20]
                + d[6] * vr[36] + d[7] * vr[37] + d[8] * vr[38];
        float t = a + xb[(size_t)c * HWP];
        __nv_bfloat16 hi = __float2bfloat16_rn(t);
        th[c] = hi;
        tl[c] = __float2bfloat16_rn(t - __bfloat162float(hi));
    }
}

// ---------------------------------------------------------------------------
// Kernel 3: 3x3 conv + ReLU via mma.sync bf16x3 implicit GEMM.
// CTA: one row y0 x 128 px. Halo: 3 x 130 px x 64c, px-stride 72 (144B,
// conflict-free). Warp tile: m16 oc x n64 px; 8 warps = 4 oc-groups x 2 px-grp.
// Per warp: 9 taps x 4 ksteps x 8 ntiles x 3 products = 864 HMMA.
// ---------------------------------------------------------------------------
#define HSTR 72                       // bf16 units per px (144 B)
#define HPX  130
#define OFF_AH 0
#define OFF_AL (3 * HPX * HSTR)       // 28080
#define OFF_WH (2 * OFF_AL)           // 56160
#define OFF_WL (OFF_WH + 64 * HSTR)   // 60768
#define SMEM3_UNITS (OFF_WL + 64 * HSTR)   // 65376 bf16 = 130752 B

__global__ __launch_bounds__(256) void conv_kernel(float* __restrict__ out) {
    extern __shared__ __nv_bfloat16 sm[];
    const int tid = threadIdx.x;
    const int wid = tid >> 5, lane = tid & 31;
    const int x0 = blockIdx.x * 128, y0 = blockIdx.y, b = blockIdx.z;

    // ---- stage halo hi/lo: [r][px][c] with px-stride 72 (src stride 64) ----
    {
        const __nv_bfloat16* srcs[2] = { g_th + (size_t)b * HWP * 64,
                                         g_tl + (size_t)b * HWP * 64 };
        #pragma unroll
        for (int hb = 0; hb < 2; hb++) {
            uint4* dst = (uint4*)(sm + (hb ? OFF_AL : OFF_AH));
            const __nv_bfloat16* s = srcs[hb];
            for (int u = tid; u < 3120; u += 256) {
                int r = u / 1040, rem = u - r * 1040;
                int px = rem >> 3, ch = rem & 7;
                int gy = y0 - 1 + r, gx = x0 - 1 + px;
                uint4 v = make_uint4(0u, 0u, 0u, 0u);
                if (gy >= 0 && gy < HH && gx >= 0 && gx < WW)
                    v = *(const uint4*)(s + ((size_t)(gy * WW + gx)) * 64 + ch * 8);
                dst[(r * HPX + px) * 9 + ch] = v;   // 72 bf16 = 9 uint4 per px
            }
        }
    }

    const int qt = lane >> 2;        // 0..7
    const int rt = lane & 3;         // 0..3
    const int ocg = wid & 3;         // oc base = ocg*16
    const int pxg = wid >> 2;        // px base = pxg*64

    float acc[8][4];
    #pragma unroll
    for (int nt = 0; nt < 8; nt++)
        #pragma unroll
        for (int i = 0; i < 4; i++) acc[nt][i] = 0.0f;

    for (int tap = 0; tap < 9; tap++) {
        __syncthreads();   // halo ready (tap 0) / prior W frag loads done
        // stage per-tap weight slice [oc][c] hi+lo, oc-stride 72
        {
            for (int u = tid; u < 1024; u += 256) {
                int half = u >> 9, oc = (u >> 3) & 63, ch = u & 7;
                const uint4* src = (const uint4*)((half ? g_wl : g_wh) + tap * 4096 + oc * 64) + ch;
                uint4* dst = (uint4*)(sm + (half ? OFF_WL : OFF_WH) + oc * HSTR) + ch;
                *dst = *src;
            }
        }
        __syncthreads();

        const int ky = tap / 3, kx = tap - ky * 3;
        const __nv_bfloat16* wh = sm + OFF_WH + (ocg * 16 + qt) * HSTR + 2 * rt;
        const __nv_bfloat16* wl = sm + OFF_WL + (ocg * 16 + qt) * HSTR + 2 * rt;
        const int arow = (ky * HPX + pxg * 64 + qt + kx) * HSTR + 2 * rt;

        #pragma unroll
        for (int ks = 0; ks < 4; ks++) {
            const int k0 = ks * 16;
            uint32_t ah0 = *(const uint32_t*)(wh + k0);
            uint32_t ah1 = *(const uint32_t*)(wh + 8 * HSTR + k0);
            uint32_t ah2 = *(const uint32_t*)(wh + k0 + 8);
            uint32_t ah3 = *(const uint32_t*)(wh + 8 * HSTR + k0 + 8);
            uint32_t al0 = *(const uint32_t*)(wl + k0);
            uint32_t al1 = *(const uint32_t*)(wl + 8 * HSTR + k0);
            uint32_t al2 = *(const uint32_t*)(wl + k0 + 8);
            uint32_t al3 = *(const uint32_t*)(wl + 8 * HSTR + k0 + 8);

            #pragma unroll
            for (int nt = 0; nt < 8; nt++) {
                const __nv_bfloat16* bh = sm + OFF_AH + arow + nt * 8 * HSTR + k0;
                const __nv_bfloat16* bl = sm + OFF_AL + arow + nt * 8 * HSTR + k0;
                uint32_t bh0 = *(const uint32_t*)(bh);
                uint32_t bh1 = *(const uint32_t*)(bh + 8);
                uint32_t bl0 = *(const uint32_t*)(bl);
                uint32_t bl1 = *(const uint32_t*)(bl + 8);
                // wh*ah + wl*ah + wh*al
                mma16816(acc[nt][0], acc[nt][1], acc[nt][2], acc[nt][3],
                         ah0, ah1, ah2, ah3, bh0, bh1);
                mma16816(acc[nt][0], acc[nt][1], acc[nt][2], acc[nt][3],
                         al0, al1, al2, al3, bh0, bh1);
                mma16816(acc[nt][0], acc[nt][1], acc[nt][2], acc[nt][3],
                         ah0, ah1, ah2, ah3, bl0, bl1);
            }
        }
    }

    // ---- epilogue: ReLU + float2 stores (contiguous pixels) ----
    float* ob = out + (size_t)b * CC * HWP + (size_t)y0 * WW + x0;
    const int oc = ocg * 16 + qt;
    #pragma unroll
    for (int nt = 0; nt < 8; nt++) {
        const int px = pxg * 64 + nt * 8 + 2 * rt;
        float2 v0 = make_float2(fmaxf(acc[nt][0], 0.f), fmaxf(acc[nt][1], 0.f));
        float2 v1 = make_float2(fmaxf(acc[nt][2], 0.f), fmaxf(acc[nt][3], 0.f));
        *(float2*)(ob + (size_t)oc * HWP + px)       = v0;
        *(float2*)(ob + (size_t)(oc + 8) * HWP + px) = v1;
    }
}

// ---------------------------------------------------------------------------
extern "C" void kernel_launch(void* const* d_in, const int* in_sizes, int n_in,
                              void* d_out, int out_size) {
    const float* x     = (const float*)d_in[0];
    const float* w_qkv = (const float*)d_in[1];
    const float* b_qkv = (const float*)d_in[2];
    const float* w_mlp = (const float*)d_in[3];
    float* out = (float*)d_out;

    const int SMEM2 = 64 * 324 * 4;
    const int SMEM3 = SMEM3_UNITS * 2;   // 130752 B
    cudaFuncSetAttribute(attn_kernel, cudaFuncAttributeMaxDynamicSharedMemorySize, SMEM2);
    cudaFuncSetAttribute(conv_kernel, cudaFuncAttributeMaxDynamicSharedMemorySize, SMEM3);

    wprep_kernel<<<144, 256>>>(w_mlp);
    qkv_kernel<<<dim3(HWP / 64, 3, BB), 256>>>(x, w_qkv, b_qkv);
    attn_kernel<<<dim3(WW / 16, HH / 16, BB), 256, SMEM2>>>(x);
    conv_kernel<<<dim3(WW / 128, HH, BB), 256, SMEM3>>>(out);
}

// round 5
// speedup vs baseline: 2.1651x; 1.5996x over previous
#include <cuda_runtime.h>
#include <cuda_bf16.h>
#include <cstdint>

#define HH 256
#define WW 256
#define HWP 65536
#define CC 64
#define BB 4

// ---------------------------------------------------------------- scratch
__device__ __align__(16) float g_q[(size_t)BB * HWP * CC];   // [b][p][c]
__device__ __align__(16) float g_k[(size_t)BB * HWP * CC];
__device__ __align__(16) float g_v[(size_t)BB * HWP * CC];
__device__ __align__(16) __nv_bfloat16 g_th[(size_t)BB * HWP * CC];  // [b][p][c] hi
__device__ __align__(16) __nv_bfloat16 g_tl[(size_t)BB * HWP * CC];  // [b][p][c] lo
__device__ uint4 g_wfh[9 * 4 * 4 * 32];   // frag-order weights hi: [tap][ocg][ks][lane]
__device__ uint4 g_wfl[9 * 4 * 4 * 32];   // lo

// ---------------------------------------------------------------------------
// mma.sync m16n8k16 bf16 (baseline PTX)
// ---------------------------------------------------------------------------
__device__ __forceinline__ void mma16816(float& d0, float& d1, float& d2, float& d3,
                                         uint32_t a0, uint32_t a1, uint32_t a2, uint32_t a3,
                                         uint32_t b0, uint32_t b1) {
    asm volatile(
        "mma.sync.aligned.m16n8k16.row.col.f32.bf16.bf16.f32 "
        "{%0,%1,%2,%3}, {%4,%5,%6,%7}, {%8,%9}, {%0,%1,%2,%3};"
        : "+f"(d0), "+f"(d1), "+f"(d2), "+f"(d3)
        : "r"(a0), "r"(a1), "r"(a2), "r"(a3), "r"(b0), "r"(b1));
}

// ---------------------------------------------------------------------------
// Kernel 0: weight prep -> bf16 hi/lo in mma fragment order.
// a0=(oc,c) a1=(oc+8,c) a2=(oc,c+8) a3=(oc+8,c+8); 32-bit reg = (c, c+1).
// ---------------------------------------------------------------------------
__device__ __forceinline__ void wpair(const float* wm, int o, int c, int tap,
                                      uint32_t& h, uint32_t& l) {
    float w0 = wm[o * 576 + c * 9 + tap];
    float w1 = wm[o * 576 + (c + 1) * 9 + tap];
    __nv_bfloat16 h0 = __float2bfloat16_rn(w0);
    __nv_bfloat16 h1 = __float2bfloat16_rn(w1);
    __nv_bfloat16 l0 = __float2bfloat16_rn(w0 - __bfloat162float(h0));
    __nv_bfloat16 l1 = __float2bfloat16_rn(w1 - __bfloat162float(h1));
    h = (uint32_t)__bfloat16_as_ushort(h0) | ((uint32_t)__bfloat16_as_ushort(h1) << 16);
    l = (uint32_t)__bfloat16_as_ushort(l0) | ((uint32_t)__bfloat16_as_ushort(l1) << 16);
}

__global__ void wprep_kernel(const float* __restrict__ wm) {
    int e = blockIdx.x * 256 + threadIdx.x;
    if (e >= 4608) return;
    int tap = e / 512, rem = e & 511;
    int ocg = rem >> 7, rem2 = rem & 127;
    int ks = rem2 >> 5, lane = rem2 & 31;
    int qt = lane >> 2, rt = lane & 3;
    int oc = ocg * 16 + qt, c = ks * 16 + 2 * rt;
    uint4 hv, lv;
    wpair(wm, oc,     c,     tap, hv.x, lv.x);
    wpair(wm, oc + 8, c,     tap, hv.y, lv.y);
    wpair(wm, oc,     c + 8, tap, hv.z, lv.z);
    wpair(wm, oc + 8, c + 8, tap, hv.w, lv.w);
    g_wfh[e] = hv;
    g_wfl[e] = lv;
}

// ---------------------------------------------------------------------------
// Kernel 1: qkv = w_qkv @ x + b; outputs channel-last via smem transpose.
// ---------------------------------------------------------------------------
__global__ __launch_bounds__(256) void qkv_kernel(const float* __restrict__ x,
                                                  const float* __restrict__ wq,
                                                  const float* __restrict__ bq) {
    __shared__ float ws[64 * 64];
    __shared__ float xs[64 * 68];   // input stage [c][p] (stride 64); out stage [p][68]
    const int p0 = blockIdx.x * 64, oc0 = blockIdx.y * 64, b = blockIdx.z;
    const int tid = threadIdx.x;

    #pragma unroll
    for (int i = 0; i < 16; i++) ws[tid + i * 256] = wq[oc0 * 64 + tid + i * 256];
    const float* xb = x + (size_t)b * CC * HWP + p0;
    #pragma unroll
    for (int i = 0; i < 16; i++) {
        int e = tid + i * 256; int c = e >> 6, p = e & 63;
        xs[e] = xb[(size_t)c * HWP + p];
    }
    __syncthreads();

    const int og = tid >> 4, pg = tid & 15;
    float acc[4][4];
    #pragma unroll
    for (int i = 0; i < 4; i++) {
        float bv = bq[oc0 + og * 4 + i];
        #pragma unroll
        for (int j = 0; j < 4; j++) acc[i][j] = bv;
    }
    #pragma unroll 8
    for (int c = 0; c < 64; c++) {
        float4 xv = *(const float4*)&xs[c * 64 + pg * 4];
        float w0 = ws[(og * 4 + 0) * 64 + c], w1 = ws[(og * 4 + 1) * 64 + c];
        float w2 = ws[(og * 4 + 2) * 64 + c], w3 = ws[(og * 4 + 3) * 64 + c];
        acc[0][0] += w0 * xv.x; acc[0][1] += w0 * xv.y; acc[0][2] += w0 * xv.z; acc[0][3] += w0 * xv.w;
        acc[1][0] += w1 * xv.x; acc[1][1] += w1 * xv.y; acc[1][2] += w1 * xv.z; acc[1][3] += w1 * xv.w;
        acc[2][0] += w2 * xv.x; acc[2][1] += w2 * xv.y; acc[2][2] += w2 * xv.z; acc[2][3] += w2 * xv.w;
        acc[3][0] += w3 * xv.x; acc[3][1] += w3 * xv.y; acc[3][2] += w3 * xv.z; acc[3][3] += w3 * xv.w;
    }

    __syncthreads();   // xs reads done
    #pragma unroll
    for (int j = 0; j < 4; j++)
        #pragma unroll
        for (int i = 0; i < 4; i++)
            xs[(pg * 4 + j) * 68 + og * 4 + i] = acc[i][j];
    __syncthreads();

    float* dst = (oc0 == 0 ? g_q : (oc0 == 64 ? g_k : g_v)) + ((size_t)b * HWP + p0) * 64;
    #pragma unroll
    for (int u = 0; u < 4; u++) {
        int e = tid + u * 256;          // 1024 float4 chunks
        int row = e >> 4, c4 = e & 15;
        *(float4*)(dst + row * 64 + c4 * 4) = *(const float4*)&xs[row * 68 + c4 * 4];
    }
}

// ---------------------------------------------------------------------------
// Kernel 2: window attention + residual (channel-last I/O).
// ---------------------------------------------------------------------------
__global__ __launch_bounds__(256) void attn_kernel(const float* __restrict__ x) {
    extern __shared__ float sb[];   // 64 * 324  ([c][halo_px])

    const int tid = threadIdx.x;
    const int lx = tid & 15, ly = tid >> 4;
    const int w0 = blockIdx.x * 16, h0 = blockIdx.y * 16;
    const int b = blockIdx.z;
    const int p = (h0 + ly) * WW + (w0 + lx);

    // ---- stage k halo: one pixel per thread, contiguous 256B gmem reads ----
    const float* kb = g_k + (size_t)b * HWP * 64;
    for (int px = tid; px < 324; px += 256) {
        int yy = px / 18, xx = px - yy * 18;
        int gy = h0 - 1 + yy, gx = w0 - 1 + xx;
        if (gy >= 0 && gy < HH && gx >= 0 && gx < WW) {
            const float4* src = (const float4*)(kb + ((size_t)(gy * WW + gx)) * 64);
            #pragma unroll
            for (int c4 = 0; c4 < 16; c4++) {
                float4 v = src[c4];
                sb[(c4 * 4 + 0) * 324 + px] = v.x;
                sb[(c4 * 4 + 1) * 324 + px] = v.y;
                sb[(c4 * 4 + 2) * 324 + px] = v.z;
                sb[(c4 * 4 + 3) * 324 + px] = v.w;
            }
        } else {
            #pragma unroll
            for (int c = 0; c < 64; c++) sb[c * 324 + px] = 0.0f;
        }
    }
    __syncthreads();

    float d[9];
    #pragma unroll
    for (int n = 0; n < 9; n++) d[n] = 0.0f;
    const float4* qp = (const float4*)(g_q + ((size_t)b * HWP + p) * 64);
    #pragma unroll 4
    for (int c4 = 0; c4 < 16; c4++) {
        float4 qv = qp[c4];
        float qs[4] = {qv.x, qv.y, qv.z, qv.w};
        #pragma unroll
        for (int i = 0; i < 4; i++) {
            const float* kr = &sb[(c4 * 4 + i) * 324 + ly * 18 + lx];
            float qc = qs[i];
            d[0] += qc * kr[0];  d[1] += qc * kr[1];  d[2] += qc * kr[2];
            d[3] += qc * kr[18]; d[4] += qc * kr[19]; d[5] += qc * kr[20];
            d[6] += qc * kr[36]; d[7] += qc * kr[37]; d[8] += qc * kr[38];
        }
    }
    float m = -1e30f;
    #pragma unroll
    for (int n = 0; n < 9; n++) { d[n] *= 0.125f; m = fmaxf(m, d[n]); }
    float s = 0.0f;
    #pragma unroll
    for (int n = 0; n < 9; n++) { d[n] = expf(d[n] - m); s += d[n]; }
    float inv = 1.0f / s;
    #pragma unroll
    for (int n = 0; n < 9; n++) d[n] *= inv;
    __syncthreads();

    // ---- stage v halo ----
    const float* vb = g_v + (size_t)b * HWP * 64;
    for (int px = tid; px < 324; px += 256) {
        int yy = px / 18, xx = px - yy * 18;
        int gy = h0 - 1 + yy, gx = w0 - 1 + xx;
        if (gy >= 0 && gy < HH && gx >= 0 && gx < WW) {
            const float4* src = (const float4*)(vb + ((size_t)(gy * WW + gx)) * 64);
            #pragma unroll
            for (int c4 = 0; c4 < 16; c4++) {
                float4 v = src[c4];
                sb[(c4 * 4 + 0) * 324 + px] = v.x;
                sb[(c4 * 4 + 1) * 324 + px] = v.y;
                sb[(c4 * 4 + 2) * 324 + px] = v.z;
                sb[(c4 * 4 + 3) * 324 + px] = v.w;
            }
        } else {
            #pragma unroll
            for (int c = 0; c < 64; c++) sb[c * 324 + px] = 0.0f;
        }
    }
    __syncthreads();

    const float* xb = x + (size_t)b * CC * HWP + p;
    __nv_bfloat16* th = g_th + ((size_t)b * HWP + p) * 64;
    __nv_bfloat16* tl = g_tl + ((size_t)b * HWP + p) * 64;
    #pragma unroll 2
    for (int c4 = 0; c4 < 16; c4++) {
        uint32_t hp0 = 0, hp1 = 0, lp0 = 0, lp1 = 0;
        #pragma unroll
        for (int i = 0; i < 4; i++) {
            int c = c4 * 4 + i;
            const float* vr = &sb[c * 324 + ly * 18 + lx];
            float a = d[0] * vr[0]  + d[1] * vr[1]  + d[2] * vr[2]
                    + d[3] * vr[18] + d[4] * vr[19] + d[5] * vr[20]
                    + d[6] * vr[36] + d[7] * vr[37] + d[8] * vr[38];
            float t = a + xb[(size_t)c * HWP];
            __nv_bfloat16 hi = __float2bfloat16_rn(t);
            __nv_bfloat16 lo = __float2bfloat16_rn(t - __bfloat162float(hi));
            uint32_t hb = __bfloat16_as_ushort(hi), lb = __bfloat16_as_ushort(lo);
            if (i < 2) { hp0 |= hb << (16 * i); lp0 |= lb << (16 * i); }
            else       { hp1 |= hb << (16 * (i - 2)); lp1 |= lb << (16 * (i - 2)); }
        }
        *(uint2*)(th + c4 * 4) = make_uint2(hp0, hp1);
        *(uint2*)(tl + c4 * 4) = make_uint2(lp0, lp1);
    }
}

// ---------------------------------------------------------------------------
// Kernel 3: 3x3 conv + ReLU via mma.sync bf16x3 implicit GEMM.
// 512 threads, 16 warps = 4 ocg x 4 pxg(32px, 4 n-tiles). Smem = halo only
// (112.3 KB -> 2 CTA/SM). Weights via LDG.128 frag loads (L1-hot). 1 sync.
// ---------------------------------------------------------------------------
#define HSTR 72
#define HPX  130
#define OFF_AH 0
#define OFF_AL (3 * HPX * HSTR)            // 28080
#define SMEM3_UNITS (2 * OFF_AL)           // 56160 bf16 = 112320 B

__global__ __launch_bounds__(512) void conv_kernel(float* __restrict__ out) {
    extern __shared__ __nv_bfloat16 sm[];
    const int tid = threadIdx.x;
    const int wid = tid >> 5, lane = tid & 31;
    const int x0 = blockIdx.x * 128, y0 = blockIdx.y, b = blockIdx.z;

    // ---- stage halo hi/lo: [r][px][c], px-stride 72 ----
    {
        const __nv_bfloat16* srcs[2] = { g_th + (size_t)b * HWP * 64,
                                         g_tl + (size_t)b * HWP * 64 };
        #pragma unroll
        for (int hb = 0; hb < 2; hb++) {
            uint4* dst = (uint4*)(sm + (hb ? OFF_AL : OFF_AH));
            const __nv_bfloat16* s = srcs[hb];
            for (int u = tid; u < 3120; u += 512) {
                int r = u / 1040, rem = u - r * 1040;
                int px = rem >> 3, ch = rem & 7;
                int gy = y0 - 1 + r, gx = x0 - 1 + px;
                uint4 v = make_uint4(0u, 0u, 0u, 0u);
                if (gy >= 0 && gy < HH && gx >= 0 && gx < WW)
                    v = *(const uint4*)(s + ((size_t)(gy * WW + gx)) * 64 + ch * 8);
                dst[(r * HPX + px) * 9 + ch] = v;
            }
        }
    }
    __syncthreads();

    const int qt = lane >> 2, rt = lane & 3;
    const int ocg = wid & 3;          // oc base = ocg*16
    const int pxg = wid >> 2;         // px base = pxg*32

    float acc[4][4];
    #pragma unroll
    for (int nt = 0; nt < 4; nt++)
        #pragma unroll
        for (int i = 0; i < 4; i++) acc[nt][i] = 0.0f;

    #pragma unroll
    for (int tap = 0; tap < 9; tap++) {
        const int ky = tap / 3, kx = tap - ky * 3;
        const int arow = (ky * HPX + pxg * 32 + qt + kx) * HSTR + 2 * rt;
        const uint4* wfh = g_wfh + (tap * 4 + ocg) * 128 + lane;
        const uint4* wfl = g_wfl + (tap * 4 + ocg) * 128 + lane;

        #pragma unroll
        for (int ks = 0; ks < 4; ks++) {
            uint4 Wh = __ldg(wfh + ks * 32);
            uint4 Wl = __ldg(wfl + ks * 32);
            const int k0 = ks * 16;
            #pragma unroll
            for (int nt = 0; nt < 4; nt++) {
                const __nv_bfloat16* bh = sm + OFF_AH + arow + nt * 8 * HSTR + k0;
                const __nv_bfloat16* bl = sm + OFF_AL + arow + nt * 8 * HSTR + k0;
                uint32_t bh0 = *(const uint32_t*)(bh);
                uint32_t bh1 = *(const uint32_t*)(bh + 8);
                uint32_t bl0 = *(const uint32_t*)(bl);
                uint32_t bl1 = *(const uint32_t*)(bl + 8);
                mma16816(acc[nt][0], acc[nt][1], acc[nt][2], acc[nt][3],
                         Wh.x, Wh.y, Wh.z, Wh.w, bh0, bh1);
                mma16816(acc[nt][0], acc[nt][1], acc[nt][2], acc[nt][3],
                         Wl.x, Wl.y, Wl.z, Wl.w, bh0, bh1);
                mma16816(acc[nt][0], acc[nt][1], acc[nt][2], acc[nt][3],
                         Wh.x, Wh.y, Wh.z, Wh.w, bl0, bl1);
            }
        }
    }

    // ---- epilogue: ReLU + float2 stores ----
    float* ob = out + (size_t)b * CC * HWP + (size_t)y0 * WW + x0;
    const int oc = ocg * 16 + qt;
    #pragma unroll
    for (int nt = 0; nt < 4; nt++) {
        const int px = pxg * 32 + nt * 8 + 2 * rt;
        float2 v0 = make_float2(fmaxf(acc[nt][0], 0.f), fmaxf(acc[nt][1], 0.f));
        float2 v1 = make_float2(fmaxf(acc[nt][2], 0.f), fmaxf(acc[nt][3], 0.f));
        *(float2*)(ob + (size_t)oc * HWP + px)       = v0;
        *(float2*)(ob + (size_t)(oc + 8) * HWP + px) = v1;
    }
}

// ---------------------------------------------------------------------------
extern "C" void kernel_launch(void* const* d_in, const int* in_sizes, int n_in,
                              void* d_out, int out_size) {
    const float* x     = (const float*)d_in[0];
    const float* w_qkv = (const float*)d_in[1];
    const float* b_qkv = (const float*)d_in[2];
    const float* w_mlp = (const float*)d_in[3];
    float* out = (float*)d_out;

    const int SMEM2 = 64 * 324 * 4;      // 82944 B
    const int SMEM3 = SMEM3_UNITS * 2;   // 112320 B
    cudaFuncSetAttribute(attn_kernel, cudaFuncAttributeMaxDynamicSharedMemorySize, SMEM2);
    cudaFuncSetAttribute(conv_kernel, cudaFuncAttributeMaxDynamicSharedMemorySize, SMEM3);

    wprep_kernel<<<18, 256>>>(w_mlp);
    qkv_kernel<<<dim3(HWP / 64, 3, BB), 256>>>(x, w_qkv, b_qkv);
    attn_kernel<<<dim3(WW / 16, HH / 16, BB), 256, SMEM2>>>(x);
    conv_kernel<<<dim3(WW / 128, HH, BB), 512, SMEM3>>>(out);
}

// round 6
// speedup vs baseline: 2.6906x; 1.2428x over previous
#include <cuda_runtime.h>
#include <cuda_bf16.h>
#include <cstdint>

#define HH 256
#define WW 256
#define HWP 65536
#define CC 64
#define BB 4

// ---------------------------------------------------------------- scratch
__device__ __align__(16) float g_q[(size_t)BB * HWP * CC];   // [b][p][c]
__device__ __align__(16) float g_k[(size_t)BB * HWP * CC];
__device__ __align__(16) float g_v[(size_t)BB * HWP * CC];
__device__ __align__(16) __nv_bfloat16 g_th[(size_t)BB * HWP * CC];  // [b][p][c] hi
__device__ __align__(16) __nv_bfloat16 g_tl[(size_t)BB * HWP * CC];  // [b][p][c] lo
__device__ uint4 g_wfh[9 * 4 * 4 * 32];    // conv weights frag-order hi
__device__ uint4 g_wfl[9 * 4 * 4 * 32];    // lo
__device__ uint4 g_wqh[12 * 4 * 32];       // qkv weights frag-order hi [ocg][ks][lane]
__device__ uint4 g_wql[12 * 4 * 32];       // lo

// ---------------------------------------------------------------------------
// mma.sync m16n8k16 bf16 (baseline PTX)
// ---------------------------------------------------------------------------
__device__ __forceinline__ void mma16816(float& d0, float& d1, float& d2, float& d3,
                                         uint32_t a0, uint32_t a1, uint32_t a2, uint32_t a3,
                                         uint32_t b0, uint32_t b1) {
    asm volatile(
        "mma.sync.aligned.m16n8k16.row.col.f32.bf16.bf16.f32 "
        "{%0,%1,%2,%3}, {%4,%5,%6,%7}, {%8,%9}, {%0,%1,%2,%3};"
        : "+f"(d0), "+f"(d1), "+f"(d2), "+f"(d3)
        : "r"(a0), "r"(a1), "r"(a2), "r"(a3), "r"(b0), "r"(b1));
}

__device__ __forceinline__ void bfpair(float w0, float w1, uint32_t& h, uint32_t& l) {
    __nv_bfloat16 h0 = __float2bfloat16_rn(w0);
    __nv_bfloat16 h1 = __float2bfloat16_rn(w1);
    __nv_bfloat16 l0 = __float2bfloat16_rn(w0 - __bfloat162float(h0));
    __nv_bfloat16 l1 = __float2bfloat16_rn(w1 - __bfloat162float(h1));
    h = (uint32_t)__bfloat16_as_ushort(h0) | ((uint32_t)__bfloat16_as_ushort(h1) << 16);
    l = (uint32_t)__bfloat16_as_ushort(l0) | ((uint32_t)__bfloat16_as_ushort(l1) << 16);
}

// ---------------------------------------------------------------------------
// Kernel 0a: conv weight prep -> frag order [tap][ocg][ks][lane]
// ---------------------------------------------------------------------------
__global__ void wprep_kernel(const float* __restrict__ wm) {
    int e = blockIdx.x * 256 + threadIdx.x;
    if (e >= 4608) return;
    int tap = e / 512, rem = e & 511;
    int ocg = rem >> 7, rem2 = rem & 127;
    int ks = rem2 >> 5, lane = rem2 & 31;
    int qt = lane >> 2, rt = lane & 3;
    int oc = ocg * 16 + qt, c = ks * 16 + 2 * rt;
    uint4 hv, lv;
    bfpair(wm[oc * 576 + c * 9 + tap],       wm[oc * 576 + (c + 1) * 9 + tap],       hv.x, lv.x);
    bfpair(wm[(oc + 8) * 576 + c * 9 + tap], wm[(oc + 8) * 576 + (c + 1) * 9 + tap], hv.y, lv.y);
    bfpair(wm[oc * 576 + (c + 8) * 9 + tap], wm[oc * 576 + (c + 9) * 9 + tap],       hv.z, lv.z);
    bfpair(wm[(oc + 8) * 576 + (c + 8) * 9 + tap], wm[(oc + 8) * 576 + (c + 9) * 9 + tap], hv.w, lv.w);
    g_wfh[e] = hv;
    g_wfl[e] = lv;
}

// ---------------------------------------------------------------------------
// Kernel 0b: qkv weight prep -> frag order [ocg(12)][ks(4)][lane(32)]
// ---------------------------------------------------------------------------
__global__ void wqprep_kernel(const float* __restrict__ wq) {
    int e = blockIdx.x * 256 + threadIdx.x;
    if (e >= 1536) return;
    int lane = e & 31, ks = (e >> 5) & 3, ocg = e >> 7;
    int qt = lane >> 2, rt = lane & 3;
    int oc = ocg * 16 + qt, c = ks * 16 + 2 * rt;
    uint4 hv, lv;
    bfpair(wq[oc * 64 + c],           wq[oc * 64 + c + 1],           hv.x, lv.x);
    bfpair(wq[(oc + 8) * 64 + c],     wq[(oc + 8) * 64 + c + 1],     hv.y, lv.y);
    bfpair(wq[oc * 64 + c + 8],       wq[oc * 64 + c + 9],           hv.z, lv.z);
    bfpair(wq[(oc + 8) * 64 + c + 8], wq[(oc + 8) * 64 + c + 9],     hv.w, lv.w);
    g_wqh[e] = hv;
    g_wql[e] = lv;
}

// ---------------------------------------------------------------------------
// Kernel 1: qkv via bf16x3 HMMA. CTA: 128 px x 192 oc, 384 thr (12 warps,
// warp = ocg). x staged to bf16 hi/lo smem (u32 px-stride 37, conflict-free).
// Epilogue: per-64oc-chunk smem transpose -> fp32 channel-last q/k/v + bias.
// ---------------------------------------------------------------------------
#define QS32 37                        // u32 stride per px
#define QKV_SMEM_B ((2 * 128 * QS32) * 4)   // 37888 B (>= 128*68*4 transpose buf)

__global__ __launch_bounds__(384, 2) void qkv_kernel(const float* __restrict__ x,
                                                     const float* __restrict__ bq) {
    extern __shared__ uint32_t qs[];
    uint32_t* xh32 = qs;
    uint32_t* xl32 = qs + 128 * QS32;
    float* tb = (float*)qs;            // reused after MMA: [px][68]

    const int tid = threadIdx.x;
    const int p0 = blockIdx.x * 128, b = blockIdx.y;
    const int wid = tid >> 5, lane = tid & 31;
    const int qt = lane >> 2, rt = lane & 3;

    // ---- stage x -> bf16 hi/lo, [px][c] pairs (coalesced gmem reads) ----
    for (int e = tid; e < 512; e += 384) {
        int px = e & 127, c0 = (e >> 7) * 16;
        const float* xp = x + (size_t)b * CC * HWP + p0 + px;
        #pragma unroll
        for (int j = 0; j < 8; j++) {
            int c = c0 + 2 * j;
            float v0 = xp[(size_t)c * HWP];
            float v1 = xp[(size_t)(c + 1) * HWP];
            uint32_t h, l;
            bfpair(v0, v1, h, l);
            xh32[px * QS32 + (c >> 1)] = h;
            xl32[px * QS32 + (c >> 1)] = l;
        }
    }
    __syncthreads();

    // ---- MMA: warp wid = ocg (0..11), all 16 n-tiles ----
    float acc[16][4];
    #pragma unroll
    for (int nt = 0; nt < 16; nt++)
        #pragma unroll
        for (int i = 0; i < 4; i++) acc[nt][i] = 0.0f;

    const uint4* wqh = g_wqh + wid * 128 + lane;
    const uint4* wql = g_wql + wid * 128 + lane;
    #pragma unroll
    for (int ks = 0; ks < 4; ks++) {
        uint4 Wh = __ldg(wqh + ks * 32);
        uint4 Wl = __ldg(wql + ks * 32);
        #pragma unroll
        for (int nt = 0; nt < 16; nt++) {
            int base = (nt * 8 + qt) * QS32 + ks * 8 + rt;
            uint32_t bh0 = xh32[base], bh1 = xh32[base + 4];
            uint32_t bl0 = xl32[base], bl1 = xl32[base + 4];
            mma16816(acc[nt][0], acc[nt][1], acc[nt][2], acc[nt][3],
                     Wh.x, Wh.y, Wh.z, Wh.w, bh0, bh1);
            mma16816(acc[nt][0], acc[nt][1], acc[nt][2], acc[nt][3],
                     Wl.x, Wl.y, Wl.z, Wl.w, bh0, bh1);
            mma16816(acc[nt][0], acc[nt][1], acc[nt][2], acc[nt][3],
                     Wh.x, Wh.y, Wh.z, Wh.w, bl0, bl1);
        }
    }
    __syncthreads();   // smem reads done; reuse as transpose buffer

    // ---- epilogue: 3 chunks (q, k, v), smem transpose + bias ----
    const int oc_global = wid * 16 + qt;    // d rows: oc_global, +8
    const float b0v = __ldg(bq + oc_global);
    const float b1v = __ldg(bq + oc_global + 8);
    #pragma unroll
    for (int chunk = 0; chunk < 3; chunk++) {
        if ((wid >> 2) == chunk) {
            const int ocl = (wid & 3) * 16 + qt;
            #pragma unroll
            for (int nt = 0; nt < 16; nt++) {
                int px = nt * 8 + 2 * rt;
                tb[px * 68 + ocl]           = acc[nt][0] + b0v;
                tb[(px + 1) * 68 + ocl]     = acc[nt][1] + b0v;
                tb[px * 68 + ocl + 8]       = acc[nt][2] + b1v;
                tb[(px + 1) * 68 + ocl + 8] = acc[nt][3] + b1v;
            }
        }
        __syncthreads();
        float* dst = (chunk == 0 ? g_q : (chunk == 1 ? g_k : g_v)) + ((size_t)b * HWP + p0) * 64;
        for (int e = tid; e < 2048; e += 384) {
            int row = e >> 4, c4 = e & 15;
            *(float4*)(dst + row * 64 + c4 * 4) = *(const float4*)&tb[row * 68 + c4 * 4];
        }
        __syncthreads();
    }
}

// ---------------------------------------------------------------------------
// Kernel 2: window attention + residual, channel-split halo (32c per pass)
// -> 41.5 KB smem -> 5 CTAs/SM.
// ---------------------------------------------------------------------------
__global__ __launch_bounds__(256) void attn_kernel(const float* __restrict__ x) {
    extern __shared__ float sb[];   // 32 * 324 floats

    const int tid = threadIdx.x;
    const int lx = tid & 15, ly = tid >> 4;
    const int w0 = blockIdx.x * 16, h0 = blockIdx.y * 16;
    const int b = blockIdx.z;
    const int p = (h0 + ly) * WW + (w0 + lx);

    float d[9];
    #pragma unroll
    for (int n = 0; n < 9; n++) d[n] = 0.0f;

    // ---- dots: two 32-channel passes over k ----
    #pragma unroll
    for (int pass = 0; pass < 2; pass++) {
        const float* kb = g_k + (size_t)b * HWP * 64 + pass * 32;
        for (int px = tid; px < 324; px += 256) {
            int yy = px / 18, xx = px - yy * 18;
            int gy = h0 - 1 + yy, gx = w0 - 1 + xx;
            if (gy >= 0 && gy < HH && gx >= 0 && gx < WW) {
                const float4* src = (const float4*)(kb + (size_t)(gy * WW + gx) * 64);
                #pragma unroll
                for (int c4 = 0; c4 < 8; c4++) {
                    float4 v = src[c4];
                    sb[(c4 * 4 + 0) * 324 + px] = v.x;
                    sb[(c4 * 4 + 1) * 324 + px] = v.y;
                    sb[(c4 * 4 + 2) * 324 + px] = v.z;
                    sb[(c4 * 4 + 3) * 324 + px] = v.w;
                }
            } else {
                #pragma unroll
                for (int c = 0; c < 32; c++) sb[c * 324 + px] = 0.0f;
            }
        }
        __syncthreads();
        const float4* qp = (const float4*)(g_q + ((size_t)b * HWP + p) * 64 + pass * 32);
        #pragma unroll 2
        for (int c4 = 0; c4 < 8; c4++) {
            float4 qv = qp[c4];
            float qsv[4] = {qv.x, qv.y, qv.z, qv.w};
            #pragma unroll
            for (int i = 0; i < 4; i++) {
                const float* kr = &sb[(c4 * 4 + i) * 324 + ly * 18 + lx];
                float qc = qsv[i];
                d[0] += qc * kr[0];  d[1] += qc * kr[1];  d[2] += qc * kr[2];
                d[3] += qc * kr[18]; d[4] += qc * kr[19]; d[5] += qc * kr[20];
                d[6] += qc * kr[36]; d[7] += qc * kr[37]; d[8] += qc * kr[38];
            }
        }
        __syncthreads();
    }

    // ---- softmax over 9 taps ----
    float m = -1e30f;
    #pragma unroll
    for (int n = 0; n < 9; n++) { d[n] *= 0.125f; m = fmaxf(m, d[n]); }
    float s = 0.0f;
    #pragma unroll
    for (int n = 0; n < 9; n++) { d[n] = expf(d[n] - m); s += d[n]; }
    float inv = 1.0f / s;
    #pragma unroll
    for (int n = 0; n < 9; n++) d[n] *= inv;

    // ---- aggregate: two 32-channel passes over v; write bf16 hi/lo ----
    const float* xb = x + (size_t)b * CC * HWP + p;
    __nv_bfloat16* th = g_th + ((size_t)b * HWP + p) * 64;
    __nv_bfloat16* tl = g_tl + ((size_t)b * HWP + p) * 64;
    #pragma unroll
    for (int pass = 0; pass < 2; pass++) {
        const float* vb = g_v + (size_t)b * HWP * 64 + pass * 32;
        for (int px = tid; px < 324; px += 256) {
            int yy = px / 18, xx = px - yy * 18;
            int gy = h0 - 1 + yy, gx = w0 - 1 + xx;
            if (gy >= 0 && gy < HH && gx >= 0 && gx < WW) {
                const float4* src = (const float4*)(vb + (size_t)(gy * WW + gx) * 64);
                #pragma unroll
                for (int c4 = 0; c4 < 8; c4++) {
                    float4 v = src[c4];
                    sb[(c4 * 4 + 0) * 324 + px] = v.x;
                    sb[(c4 * 4 + 1) * 324 + px] = v.y;
                    sb[(c4 * 4 + 2) * 324 + px] = v.z;
                    sb[(c4 * 4 + 3) * 324 + px] = v.w;
                }
            } else {
                #pragma unroll
                for (int c = 0; c < 32; c++) sb[c * 324 + px] = 0.0f;
            }
        }
        __syncthreads();
        #pragma unroll 2
        for (int c4 = 0; c4 < 8; c4++) {
            uint32_t hp0 = 0, hp1 = 0, lp0 = 0, lp1 = 0;
            #pragma unroll
            for (int i = 0; i < 4; i++) {
                int c = c4 * 4 + i;
                const float* vr = &sb[c * 324 + ly * 18 + lx];
                float a = d[0] * vr[0]  + d[1] * vr[1]  + d[2] * vr[2]
                        + d[3] * vr[18] + d[4] * vr[19] + d[5] * vr[20]
                        + d[6] * vr[36] + d[7] * vr[37] + d[8] * vr[38];
                float t = a + xb[(size_t)(pass * 32 + c) * HWP];
                __nv_bfloat16 hi = __float2bfloat16_rn(t);
                __nv_bfloat16 lo = __float2bfloat16_rn(t - __bfloat162float(hi));
                uint32_t hb = __bfloat16_as_ushort(hi), lb = __bfloat16_as_ushort(lo);
                if (i < 2) { hp0 |= hb << (16 * i); lp0 |= lb << (16 * i); }
                else       { hp1 |= hb << (16 * (i - 2)); lp1 |= lb << (16 * (i - 2)); }
            }
            *(uint2*)(th + pass * 32 + c4 * 4) = make_uint2(hp0, hp1);
            *(uint2*)(tl + pass * 32 + c4 * 4) = make_uint2(lp0, lp1);
        }
        __syncthreads();
    }
}

// ---------------------------------------------------------------------------
// Kernel 3: 3x3 conv + ReLU via mma.sync bf16x3 implicit GEMM (R5 version).
// ---------------------------------------------------------------------------
#define HSTR 72
#define HPX  130
#define OFF_AH 0
#define OFF_AL (3 * HPX * HSTR)            // 28080
#define SMEM3_UNITS (2 * OFF_AL)           // 112320 B

__global__ __launch_bounds__(512) void conv_kernel(float* __restrict__ out) {
    extern __shared__ __nv_bfloat16 sm[];
    const int tid = threadIdx.x;
    const int wid = tid >> 5, lane = tid & 31;
    const int x0 = blockIdx.x * 128, y0 = blockIdx.y, b = blockIdx.z;

    {
        const __nv_bfloat16* srcs[2] = { g_th + (size_t)b * HWP * 64,
                                         g_tl + (size_t)b * HWP * 64 };
        #pragma unroll
        for (int hb = 0; hb < 2; hb++) {
            uint4* dst = (uint4*)(sm + (hb ? OFF_AL : OFF_AH));
            const __nv_bfloat16* s = srcs[hb];
            for (int u = tid; u < 3120; u += 512) {
                int r = u / 1040, rem = u - r * 1040;
                int px = rem >> 3, ch = rem & 7;
                int gy = y0 - 1 + r, gx = x0 - 1 + px;
                uint4 v = make_uint4(0u, 0u, 0u, 0u);
                if (gy >= 0 && gy < HH && gx >= 0 && gx < WW)
                    v = *(const uint4*)(s + ((size_t)(gy * WW + gx)) * 64 + ch * 8);
                dst[(r * HPX + px) * 9 + ch] = v;
            }
        }
    }
    __syncthreads();

    const int qt = lane >> 2, rt = lane & 3;
    const int ocg = wid & 3;
    const int pxg = wid >> 2;

    float acc[4][4];
    #pragma unroll
    for (int nt = 0; nt < 4; nt++)
        #pragma unroll
        for (int i = 0; i < 4; i++) acc[nt][i] = 0.0f;

    #pragma unroll
    for (int tap = 0; tap < 9; tap++) {
        const int ky = tap / 3, kx = tap - ky * 3;
        const int arow = (ky * HPX + pxg * 32 + qt + kx) * HSTR + 2 * rt;
        const uint4* wfh = g_wfh + (tap * 4 + ocg) * 128 + lane;
        const uint4* wfl = g_wfl + (tap * 4 + ocg) * 128 + lane;

        #pragma unroll
        for (int ks = 0; ks < 4; ks++) {
            uint4 Wh = __ldg(wfh + ks * 32);
            uint4 Wl = __ldg(wfl + ks * 32);
            const int k0 = ks * 16;
            #pragma unroll
            for (int nt = 0; nt < 4; nt++) {
                const __nv_bfloat16* bh = sm + OFF_AH + arow + nt * 8 * HSTR + k0;
                const __nv_bfloat16* bl = sm + OFF_AL + arow + nt * 8 * HSTR + k0;
                uint32_t bh0 = *(const uint32_t*)(bh);
                uint32_t bh1 = *(const uint32_t*)(bh + 8);
                uint32_t bl0 = *(const uint32_t*)(bl);
                uint32_t bl1 = *(const uint32_t*)(bl + 8);
                mma16816(acc[nt][0], acc[nt][1], acc[nt][2], acc[nt][3],
                         Wh.x, Wh.y, Wh.z, Wh.w, bh0, bh1);
                mma16816(acc[nt][0], acc[nt][1], acc[nt][2], acc[nt][3],
                         Wl.x, Wl.y, Wl.z, Wl.w, bh0, bh1);
                mma16816(acc[nt][0], acc[nt][1], acc[nt][2], acc[nt][3],
                         Wh.x, Wh.y, Wh.z, Wh.w, bl0, bl1);
            }
        }
    }

    float* ob = out + (size_t)b * CC * HWP + (size_t)y0 * WW + x0;
    const int oc = ocg * 16 + qt;
    #pragma unroll
    for (int nt = 0; nt < 4; nt++) {
        const int px = pxg * 32 + nt * 8 + 2 * rt;
        float2 v0 = make_float2(fmaxf(acc[nt][0], 0.f), fmaxf(acc[nt][1], 0.f));
        float2 v1 = make_float2(fmaxf(acc[nt][2], 0.f), fmaxf(acc[nt][3], 0.f));
        *(float2*)(ob + (size_t)oc * HWP + px)       = v0;
        *(float2*)(ob + (size_t)(oc + 8) * HWP + px) = v1;
    }
}

// ---------------------------------------------------------------------------
extern "C" void kernel_launch(void* const* d_in, const int* in_sizes, int n_in,
                              void* d_out, int out_size) {
    const float* x     = (const float*)d_in[0];
    const float* w_qkv = (const float*)d_in[1];
    const float* b_qkv = (const float*)d_in[2];
    const float* w_mlp = (const float*)d_in[3];
    float* out = (float*)d_out;

    const int SMEM2 = 32 * 324 * 4;      // 41472 B
    const int SMEM3 = SMEM3_UNITS * 2;   // 112320 B
    cudaFuncSetAttribute(qkv_kernel,  cudaFuncAttributeMaxDynamicSharedMemorySize, QKV_SMEM_B);
    cudaFuncSetAttribute(attn_kernel, cudaFuncAttributeMaxDynamicSharedMemorySize, SMEM2);
    cudaFuncSetAttribute(conv_kernel, cudaFuncAttributeMaxDynamicSharedMemorySize, SMEM3);

    wprep_kernel<<<18, 256>>>(w_mlp);
    wqprep_kernel<<<6, 256>>>(w_qkv);
    qkv_kernel<<<dim3(HWP / 128, BB), 384, QKV_SMEM_B>>>(x, b_qkv);
    attn_kernel<<<dim3(WW / 16, HH / 16, BB), 256, SMEM2>>>(x);
    conv_kernel<<<dim3(WW / 128, HH, BB), 512, SMEM3>>>(out);
}

// round 7
// speedup vs baseline: 3.2796x; 1.2189x over previous
#include <cuda_runtime.h>
#include <cuda_bf16.h>
#include <cstdint>

#define HH 256
#define WW 256
#define HWP 65536
#define CC 64
#define BB 4

// ---------------------------------------------------------------- scratch
__device__ __align__(16) float g_q[(size_t)BB * HWP * CC];   // [b][p][c]
__device__ __align__(16) float g_k[(size_t)BB * HWP * CC];
__device__ __align__(16) float g_v[(size_t)BB * HWP * CC];
__device__ __align__(16) __nv_bfloat16 g_th[(size_t)BB * HWP * CC];  // [b][p][c] hi
__device__ __align__(16) __nv_bfloat16 g_tl[(size_t)BB * HWP * CC];  // [b][p][c] lo
__device__ __align__(16) uint32_t g_xh[(size_t)BB * HWP * 32];       // x bf16-pair hi [b][p][32]
__device__ __align__(16) uint32_t g_xl[(size_t)BB * HWP * 32];       // lo
__device__ uint4 g_wfh[9 * 4 * 4 * 32];    // conv weights frag-order hi
__device__ uint4 g_wfl[9 * 4 * 4 * 32];    // lo
__device__ uint4 g_wqh[12 * 4 * 32];       // qkv weights frag-order hi
__device__ uint4 g_wql[12 * 4 * 32];       // lo

#define BFLO(u) __uint_as_float((u) << 16)
#define BFHI(u) __uint_as_float((u) & 0xffff0000u)

// ---------------------------------------------------------------------------
__device__ __forceinline__ void mma16816(float& d0, float& d1, float& d2, float& d3,
                                         uint32_t a0, uint32_t a1, uint32_t a2, uint32_t a3,
                                         uint32_t b0, uint32_t b1) {
    asm volatile(
        "mma.sync.aligned.m16n8k16.row.col.f32.bf16.bf16.f32 "
        "{%0,%1,%2,%3}, {%4,%5,%6,%7}, {%8,%9}, {%0,%1,%2,%3};"
        : "+f"(d0), "+f"(d1), "+f"(d2), "+f"(d3)
        : "r"(a0), "r"(a1), "r"(a2), "r"(a3), "r"(b0), "r"(b1));
}

__device__ __forceinline__ void bfpair(float w0, float w1, uint32_t& h, uint32_t& l) {
    __nv_bfloat16 h0 = __float2bfloat16_rn(w0);
    __nv_bfloat16 h1 = __float2bfloat16_rn(w1);
    __nv_bfloat16 l0 = __float2bfloat16_rn(w0 - __bfloat162float(h0));
    __nv_bfloat16 l1 = __float2bfloat16_rn(w1 - __bfloat162float(h1));
    h = (uint32_t)__bfloat16_as_ushort(h0) | ((uint32_t)__bfloat16_as_ushort(h1) << 16);
    l = (uint32_t)__bfloat16_as_ushort(l0) | ((uint32_t)__bfloat16_as_ushort(l1) << 16);
}

// ---------------------------------------------------------------------------
// Kernel 0a: conv weight prep -> frag order [tap][ocg][ks][lane]
// ---------------------------------------------------------------------------
__global__ void wprep_kernel(const float* __restrict__ wm) {
    int e = blockIdx.x * 256 + threadIdx.x;
    if (e >= 4608) return;
    int tap = e / 512, rem = e & 511;
    int ocg = rem >> 7, rem2 = rem & 127;
    int ks = rem2 >> 5, lane = rem2 & 31;
    int qt = lane >> 2, rt = lane & 3;
    int oc = ocg * 16 + qt, c = ks * 16 + 2 * rt;
    uint4 hv, lv;
    bfpair(wm[oc * 576 + c * 9 + tap],       wm[oc * 576 + (c + 1) * 9 + tap],       hv.x, lv.x);
    bfpair(wm[(oc + 8) * 576 + c * 9 + tap], wm[(oc + 8) * 576 + (c + 1) * 9 + tap], hv.y, lv.y);
    bfpair(wm[oc * 576 + (c + 8) * 9 + tap], wm[oc * 576 + (c + 9) * 9 + tap],       hv.z, lv.z);
    bfpair(wm[(oc + 8) * 576 + (c + 8) * 9 + tap], wm[(oc + 8) * 576 + (c + 9) * 9 + tap], hv.w, lv.w);
    g_wfh[e] = hv;
    g_wfl[e] = lv;
}

// ---------------------------------------------------------------------------
// Kernel 0b: qkv weight prep -> frag order [ocg(12)][ks(4)][lane(32)]
// ---------------------------------------------------------------------------
__global__ void wqprep_kernel(const float* __restrict__ wq) {
    int e = blockIdx.x * 256 + threadIdx.x;
    if (e >= 1536) return;
    int lane = e & 31, ks = (e >> 5) & 3, ocg = e >> 7;
    int qt = lane >> 2, rt = lane & 3;
    int oc = ocg * 16 + qt, c = ks * 16 + 2 * rt;
    uint4 hv, lv;
    bfpair(wq[oc * 64 + c],           wq[oc * 64 + c + 1],           hv.x, lv.x);
    bfpair(wq[(oc + 8) * 64 + c],     wq[(oc + 8) * 64 + c + 1],     hv.y, lv.y);
    bfpair(wq[oc * 64 + c + 8],       wq[oc * 64 + c + 9],           hv.z, lv.z);
    bfpair(wq[(oc + 8) * 64 + c + 8], wq[(oc + 8) * 64 + c + 9],     hv.w, lv.w);
    g_wqh[e] = hv;
    g_wql[e] = lv;
}

// ---------------------------------------------------------------------------
// Kernel 1: qkv via bf16x3 HMMA + export of x bf16 hi/lo pairs (channel-last).
// ---------------------------------------------------------------------------
#define QS32 37
#define QKV_SMEM_B ((2 * 128 * QS32) * 4)   // 37888 B

__global__ __launch_bounds__(384, 2) void qkv_kernel(const float* __restrict__ x,
                                                     const float* __restrict__ bq) {
    extern __shared__ uint32_t qs[];
    uint32_t* xh32 = qs;
    uint32_t* xl32 = qs + 128 * QS32;
    float* tb = (float*)qs;

    const int tid = threadIdx.x;
    const int p0 = blockIdx.x * 128, b = blockIdx.y;
    const int wid = tid >> 5, lane = tid & 31;
    const int qt = lane >> 2, rt = lane & 3;

    for (int e = tid; e < 512; e += 384) {
        int px = e & 127, c0 = (e >> 7) * 16;
        const float* xp = x + (size_t)b * CC * HWP + p0 + px;
        #pragma unroll
        for (int j = 0; j < 8; j++) {
            int c = c0 + 2 * j;
            float v0 = xp[(size_t)c * HWP];
            float v1 = xp[(size_t)(c + 1) * HWP];
            uint32_t h, l;
            bfpair(v0, v1, h, l);
            xh32[px * QS32 + (c >> 1)] = h;
            xl32[px * QS32 + (c >> 1)] = l;
        }
    }
    __syncthreads();

    float acc[16][4];
    #pragma unroll
    for (int nt = 0; nt < 16; nt++)
        #pragma unroll
        for (int i = 0; i < 4; i++) acc[nt][i] = 0.0f;

    const uint4* wqh = g_wqh + wid * 128 + lane;
    const uint4* wql = g_wql + wid * 128 + lane;
    #pragma unroll
    for (int ks = 0; ks < 4; ks++) {
        uint4 Wh = __ldg(wqh + ks * 32);
        uint4 Wl = __ldg(wql + ks * 32);
        #pragma unroll
        for (int nt = 0; nt < 16; nt++) {
            int base = (nt * 8 + qt) * QS32 + ks * 8 + rt;
            uint32_t bh0 = xh32[base], bh1 = xh32[base + 4];
            uint32_t bl0 = xl32[base], bl1 = xl32[base + 4];
            mma16816(acc[nt][0], acc[nt][1], acc[nt][2], acc[nt][3],
                     Wh.x, Wh.y, Wh.z, Wh.w, bh0, bh1);
            mma16816(acc[nt][0], acc[nt][1], acc[nt][2], acc[nt][3],
                     Wl.x, Wl.y, Wl.z, Wl.w, bh0, bh1);
            mma16816(acc[nt][0], acc[nt][1], acc[nt][2], acc[nt][3],
                     Wh.x, Wh.y, Wh.z, Wh.w, bl0, bl1);
        }
    }
    __syncthreads();

    // export x bf16 pairs (coalesced) before smem reuse
    {
        uint32_t* xh = g_xh + ((size_t)b * HWP + p0) * 32;
        uint32_t* xl = g_xl + ((size_t)b * HWP + p0) * 32;
        for (int e = tid; e < 4096; e += 384) {
            int px = e >> 5, c = e & 31;
            xh[e] = xh32[px * QS32 + c];
            xl[e] = xl32[px * QS32 + c];
        }
    }
    __syncthreads();

    const int oc_global = wid * 16 + qt;
    const float b0v = __ldg(bq + oc_global);
    const float b1v = __ldg(bq + oc_global + 8);
    #pragma unroll
    for (int chunk = 0; chunk < 3; chunk++) {
        if ((wid >> 2) == chunk) {
            const int ocl = (wid & 3) * 16 + qt;
            #pragma unroll
            for (int nt = 0; nt < 16; nt++) {
                int px = nt * 8 + 2 * rt;
                tb[px * 68 + ocl]           = acc[nt][0] + b0v;
                tb[(px + 1) * 68 + ocl]     = acc[nt][1] + b0v;
                tb[px * 68 + ocl + 8]       = acc[nt][2] + b1v;
                tb[(px + 1) * 68 + ocl + 8] = acc[nt][3] + b1v;
            }
        }
        __syncthreads();
        float* dst = (chunk == 0 ? g_q : (chunk == 1 ? g_k : g_v)) + ((size_t)b * HWP + p0) * 64;
        for (int e = tid; e < 2048; e += 384) {
            int row = e >> 4, c4 = e & 15;
            *(float4*)(dst + row * 64 + c4 * 4) = *(const float4*)&tb[row * 68 + c4 * 4];
        }
        __syncthreads();
    }
}

// ---------------------------------------------------------------------------
// Kernel 2: window attention + residual.
// Tile 16x4 px; halo 18x6 = 108 px, channel-last (stride 68 floats), k+v
// buffers (57.4 KB, 3 CTAs/SM). Warp = 4 px x 8 channel-lanes; dots via
// LDS.128 + 8-lane shfl.bfly reduce; __expf softmax; residual from g_xh/g_xl.
// ---------------------------------------------------------------------------
#define APS 68
#define HALO_PX 108        // 18 * 6
#define SMEM2 (2 * HALO_PX * APS * 4)   // 58752 B

__global__ __launch_bounds__(256) void attn_kernel() {
    extern __shared__ float sb[];
    float* kbuf = sb;
    float* vbuf = sb + HALO_PX * APS;

    const int tid = threadIdx.x;
    const int wid = tid >> 5, lane = tid & 31;
    const int g = lane >> 3, cl = lane & 7;
    const int w0 = blockIdx.x * 16, h0 = blockIdx.y * 4;
    const int b = blockIdx.z;

    // ---- stage k & v halos (channel-last, float4, zero-padded) ----
    for (int u = tid; u < HALO_PX * 16; u += 256) {
        int hp = u >> 4, c4 = u & 15;
        int hy = hp / 18, hx = hp - hy * 18;
        int gy = h0 - 1 + hy, gx = w0 - 1 + hx;
        float4 kv = make_float4(0.f, 0.f, 0.f, 0.f), vv = kv;
        if (gy >= 0 && gy < HH && gx >= 0 && gx < WW) {
            size_t o = ((size_t)b * HWP + gy * WW + gx) * 64 + c4 * 4;
            kv = *(const float4*)(g_k + o);
            vv = *(const float4*)(g_v + o);
        }
        *(float4*)(kbuf + hp * APS + c4 * 4) = kv;
        *(float4*)(vbuf + hp * APS + c4 * 4) = vv;
    }
    __syncthreads();

    #pragma unroll
    for (int it = 0; it < 2; it++) {
        const int pxi = it * 32 + wid * 4 + g;
        const int tx = pxi & 15, ty = pxi >> 4;
        const int p = (h0 + ty) * WW + w0 + tx;

        const float4* qp = (const float4*)(g_q + ((size_t)b * HWP + p) * 64);
        float4 q0 = qp[cl], q1 = qp[cl + 8];

        const int base = ((ty + 1) * 18 + tx + 1) * APS + cl * 4;

        float d[9];
        #pragma unroll
        for (int n = 0; n < 9; n++) {
            int dy = n / 3 - 1, dx = n - (n / 3) * 3 - 1;
            const float* kr = kbuf + base + (dy * 18 + dx) * APS;
            float4 k0 = *(const float4*)kr;
            float4 k1 = *(const float4*)(kr + 32);
            d[n] = q0.x * k0.x + q0.y * k0.y + q0.z * k0.z + q0.w * k0.w
                 + q1.x * k1.x + q1.y * k1.y + q1.z * k1.z + q1.w * k1.w;
        }
        #pragma unroll
        for (int ofs = 4; ofs > 0; ofs >>= 1)
            #pragma unroll
            for (int n = 0; n < 9; n++)
                d[n] += __shfl_xor_sync(0xffffffffu, d[n], ofs);

        float m = -1e30f;
        #pragma unroll
        for (int n = 0; n < 9; n++) { d[n] *= 0.125f; m = fmaxf(m, d[n]); }
        float s = 0.0f;
        #pragma unroll
        for (int n = 0; n < 9; n++) { d[n] = __expf(d[n] - m); s += d[n]; }
        float inv = 1.0f / s;
        #pragma unroll
        for (int n = 0; n < 9; n++) d[n] *= inv;

        float4 o0 = make_float4(0.f, 0.f, 0.f, 0.f), o1 = o0;
        #pragma unroll
        for (int n = 0; n < 9; n++) {
            int dy = n / 3 - 1, dx = n - (n / 3) * 3 - 1;
            const float* vr = vbuf + base + (dy * 18 + dx) * APS;
            float4 v0 = *(const float4*)vr;
            float4 v1 = *(const float4*)(vr + 32);
            float a = d[n];
            o0.x += a * v0.x; o0.y += a * v0.y; o0.z += a * v0.z; o0.w += a * v0.w;
            o1.x += a * v1.x; o1.y += a * v1.y; o1.z += a * v1.z; o1.w += a * v1.w;
        }

        // residual from bf16 hi/lo pairs
        const uint32_t* xhp = g_xh + ((size_t)b * HWP + p) * 32;
        const uint32_t* xlp = g_xl + ((size_t)b * HWP + p) * 32;
        uint2 h0p = *(const uint2*)(xhp + cl * 2);
        uint2 l0p = *(const uint2*)(xlp + cl * 2);
        uint2 h1p = *(const uint2*)(xhp + 16 + cl * 2);
        uint2 l1p = *(const uint2*)(xlp + 16 + cl * 2);

        float t0 = o0.x + BFLO(h0p.x) + BFLO(l0p.x);
        float t1 = o0.y + BFHI(h0p.x) + BFHI(l0p.x);
        float t2 = o0.z + BFLO(h0p.y) + BFLO(l0p.y);
        float t3 = o0.w + BFHI(h0p.y) + BFHI(l0p.y);
        float t4 = o1.x + BFLO(h1p.x) + BFLO(l1p.x);
        float t5 = o1.y + BFHI(h1p.x) + BFHI(l1p.x);
        float t6 = o1.z + BFLO(h1p.y) + BFLO(l1p.y);
        float t7 = o1.w + BFHI(h1p.y) + BFHI(l1p.y);

        uint2 oh0, ol0, oh1, ol1;
        bfpair(t0, t1, oh0.x, ol0.x);
        bfpair(t2, t3, oh0.y, ol0.y);
        bfpair(t4, t5, oh1.x, ol1.x);
        bfpair(t6, t7, oh1.y, ol1.y);

        __nv_bfloat16* th = g_th + ((size_t)b * HWP + p) * 64;
        __nv_bfloat16* tl = g_tl + ((size_t)b * HWP + p) * 64;
        *(uint2*)(th + cl * 4)      = oh0;
        *(uint2*)(th + 32 + cl * 4) = oh1;
        *(uint2*)(tl + cl * 4)      = ol0;
        *(uint2*)(tl + 32 + cl * 4) = ol1;
    }
}

// ---------------------------------------------------------------------------
// Kernel 3: 3x3 conv + ReLU via mma.sync bf16x3 implicit GEMM (unchanged).
// ---------------------------------------------------------------------------
#define HSTR 72
#define HPX  130
#define OFF_AH 0
#define OFF_AL (3 * HPX * HSTR)
#define SMEM3_UNITS (2 * OFF_AL)

__global__ __launch_bounds__(512) void conv_kernel(float* __restrict__ out) {
    extern __shared__ __nv_bfloat16 sm[];
    const int tid = threadIdx.x;
    const int wid = tid >> 5, lane = tid & 31;
    const int x0 = blockIdx.x * 128, y0 = blockIdx.y, b = blockIdx.z;

    {
        const __nv_bfloat16* srcs[2] = { g_th + (size_t)b * HWP * 64,
                                         g_tl + (size_t)b * HWP * 64 };
        #pragma unroll
        for (int hb = 0; hb < 2; hb++) {
            uint4* dst = (uint4*)(sm + (hb ? OFF_AL : OFF_AH));
            const __nv_bfloat16* s = srcs[hb];
            for (int u = tid; u < 3120; u += 512) {
                int r = u / 1040, rem = u - r * 1040;
                int px = rem >> 3, ch = rem & 7;
                int gy = y0 - 1 + r, gx = x0 - 1 + px;
                uint4 v = make_uint4(0u, 0u, 0u, 0u);
                if (gy >= 0 && gy < HH && gx >= 0 && gx < WW)
                    v = *(const uint4*)(s + ((size_t)(gy * WW + gx)) * 64 + ch * 8);
                dst[(r * HPX + px) * 9 + ch] = v;
            }
        }
    }
    __syncthreads();

    const int qt = lane >> 2, rt = lane & 3;
    const int ocg = wid & 3;
    const int pxg = wid >> 2;

    float acc[4][4];
    #pragma unroll
    for (int nt = 0; nt < 4; nt++)
        #pragma unroll
        for (int i = 0; i < 4; i++) acc[nt][i] = 0.0f;

    #pragma unroll
    for (int tap = 0; tap < 9; tap++) {
        const int ky = tap / 3, kx = tap - ky * 3;
        const int arow = (ky * HPX + pxg * 32 + qt + kx) * HSTR + 2 * rt;
        const uint4* wfh = g_wfh + (tap * 4 + ocg) * 128 + lane;
        const uint4* wfl = g_wfl + (tap * 4 + ocg) * 128 + lane;

        #pragma unroll
        for (int ks = 0; ks < 4; ks++) {
            uint4 Wh = __ldg(wfh + ks * 32);
            uint4 Wl = __ldg(wfl + ks * 32);
            const int k0 = ks * 16;
            #pragma unroll
            for (int nt = 0; nt < 4; nt++) {
                const __nv_bfloat16* bh = sm + OFF_AH + arow + nt * 8 * HSTR + k0;
                const __nv_bfloat16* bl = sm + OFF_AL + arow + nt * 8 * HSTR + k0;
                uint32_t bh0 = *(const uint32_t*)(bh);
                uint32_t bh1 = *(const uint32_t*)(bh + 8);
                uint32_t bl0 = *(const uint32_t*)(bl);
                uint32_t bl1 = *(const uint32_t*)(bl + 8);
                mma16816(acc[nt][0], acc[nt][1], acc[nt][2], acc[nt][3],
                         Wh.x, Wh.y, Wh.z, Wh.w, bh0, bh1);
                mma16816(acc[nt][0], acc[nt][1], acc[nt][2], acc[nt][3],
                         Wl.x, Wl.y, Wl.z, Wl.w, bh0, bh1);
                mma16816(acc[nt][0], acc[nt][1], acc[nt][2], acc[nt][3],
                         Wh.x, Wh.y, Wh.z, Wh.w, bl0, bl1);
            }
        }
    }

    float* ob = out + (size_t)b * CC * HWP + (size_t)y0 * WW + x0;
    const int oc = ocg * 16 + qt;
    #pragma unroll
    for (int nt = 0; nt < 4; nt++) {
        const int px = pxg * 32 + nt * 8 + 2 * rt;
        float2 v0 = make_float2(fmaxf(acc[nt][0], 0.f), fmaxf(acc[nt][1], 0.f));
        float2 v1 = make_float2(fmaxf(acc[nt][2], 0.f), fmaxf(acc[nt][3], 0.f));
        *(float2*)(ob + (size_t)oc * HWP + px)       = v0;
        *(float2*)(ob + (size_t)(oc + 8) * HWP + px) = v1;
    }
}

// ---------------------------------------------------------------------------
extern "C" void kernel_launch(void* const* d_in, const int* in_sizes, int n_in,
                              void* d_out, int out_size) {
    const float* x     = (const float*)d_in[0];
    const float* w_qkv = (const float*)d_in[1];
    const float* b_qkv = (const float*)d_in[2];
    const float* w_mlp = (const float*)d_in[3];
    float* out = (float*)d_out;

    const int SMEM3 = SMEM3_UNITS * 2;
    cudaFuncSetAttribute(qkv_kernel,  cudaFuncAttributeMaxDynamicSharedMemorySize, QKV_SMEM_B);
    cudaFuncSetAttribute(attn_kernel, cudaFuncAttributeMaxDynamicSharedMemorySize, SMEM2);
    cudaFuncSetAttribute(conv_kernel, cudaFuncAttributeMaxDynamicSharedMemorySize, SMEM3);

    wprep_kernel<<<18, 256>>>(w_mlp);
    wqprep_kernel<<<6, 256>>>(w_qkv);
    qkv_kernel<<<dim3(HWP / 128, BB), 384, QKV_SMEM_B>>>(x, b_qkv);
    attn_kernel<<<dim3(WW / 16, HH / 4, BB), 256, SMEM2>>>();
    conv_kernel<<<dim3(WW / 128, HH, BB), 512, SMEM3>>>(out);
}